// round 11
// baseline (speedup 1.0000x reference)
#include <cuda_runtime.h>
#include <math.h>

#define B_ 32
#define C_ 64
#define L_ 8192
#define W_ 32
#define HOP_ 8
#define NW_ 1021          // (8192-32)/8 + 1 ; last start == L-W so no append
#define NBINS_ 4096       // total spectral bins per batch (sum n_i/2 == L/2)
#define BCAP_ 1088        // dft block capacity per batch
#define MAXSEG_ 1025
#define MAXTOK_ 2048
#define EB 32             // DP end-batch size
#define EG 8              // DP sub-group size (register working set)
#define NG (EB / EG)      // sub-groups per round
#define DPT 512           // DP threads per block
#define NWARP (DPT / 32)

// ================= double-single (df64) arithmetic, fast-math-proof =============
__device__ __forceinline__ float2 ds_from_double(double d) {
    float h = (float)d;
    return make_float2(h, (float)(d - (double)h));
}
__device__ __forceinline__ double ds_to_double(float2 a) {
    return (double)a.x + (double)a.y;
}
__device__ __forceinline__ float2 ds_add(float2 a, float2 b) {
    float s = __fadd_rn(a.x, b.x);
    float v = __fadd_rn(s, -a.x);
    float e = __fadd_rn(__fadd_rn(a.x, -__fadd_rn(s, -v)),
                        __fadd_rn(b.x, -v));
    e = __fadd_rn(e, __fadd_rn(a.y, b.y));
    float hi = __fadd_rn(s, e);
    float lo = __fadd_rn(e, -__fadd_rn(hi, -s));
    return make_float2(hi, lo);
}
__device__ __forceinline__ float2 ds_neg(float2 a) { return make_float2(-a.x, -a.y); }
__device__ __forceinline__ float2 ds_sub(float2 a, float2 b) { return ds_add(a, ds_neg(b)); }
// (a,0) - b  : exact-float minus df64
__device__ __forceinline__ float2 ds_fsub(float a, float2 b) {
    float bx = -b.x;
    float s = __fadd_rn(a, bx);
    float v = __fadd_rn(s, -a);
    float e = __fadd_rn(__fadd_rn(a, -__fadd_rn(s, -v)),
                        __fadd_rn(bx, -v));
    e = __fadd_rn(e, -b.y);
    float hi = __fadd_rn(s, e);
    float lo = __fadd_rn(e, -__fadd_rn(hi, -s));
    return make_float2(hi, lo);
}
__device__ __forceinline__ float2 ds_mul(float2 a, float2 b) {
    float p = __fmul_rn(a.x, b.x);
    float e = __fmaf_rn(a.x, b.x, -p);
    e = __fmaf_rn(a.x, b.y, e);
    e = __fmaf_rn(a.y, b.x, e);
    float hi = __fadd_rn(p, e);
    float lo = __fadd_rn(e, -__fadd_rn(hi, -p));
    return make_float2(hi, lo);
}
__device__ __forceinline__ float2 ds_muf(float a, float2 b) {   // exact-float * df64
    float p = __fmul_rn(a, b.x);
    float e = __fmaf_rn(a, b.x, -p);
    e = __fmaf_rn(a, b.y, e);
    float hi = __fadd_rn(p, e);
    float lo = __fadd_rn(e, -__fadd_rn(hi, -p));
    return make_float2(hi, lo);
}
__device__ __forceinline__ bool ds_lt(float2 a, float2 b) {
    return (a.x < b.x) || (a.x == b.x && a.y < b.y);
}

// ---------------- device scratch (static: no allocation allowed) ----------------
__device__ float  g_aggf[B_][L_];
__device__ double g_feat[B_][NW_][3];
__device__ int    g_bnd[B_][MAXSEG_ + 1];
__device__ int    g_nseg[B_];
__device__ int    g_boff[B_][MAXSEG_ + 1];
__device__ int    g_blkoff[B_][MAXSEG_ + 1];
__device__ double g_pw[B_][NBINS_];
__device__ double g_sdom[B_][MAXSEG_];
__device__ double g_sbw[B_][MAXSEG_];
__device__ int    g_spl[B_][MAXSEG_];
__device__ int    g_snp[B_][MAXSEG_];
__device__ int    g_toff[B_][MAXSEG_ + 1];
__device__ int    g_ntok[B_];
__device__ int    g_tok[B_][MAXTOK_][2];

// ---------------- 1) channel mean (fp32 sequential like numpy; exact in fp32) ----
__global__ void k_agg(const float* __restrict__ x) {
    int t = blockIdx.x * blockDim.x + threadIdx.x;
    int b = blockIdx.y;
    if (t >= L_) return;
    const float* xp = x + (size_t)b * C_ * L_ + t;
    float s = 0.0f;
#pragma unroll 8
    for (int c = 0; c < C_; ++c) s += xp[(size_t)c * L_];
    g_aggf[b][t] = s * (1.0f / 64.0f);
}

// ---------------- 2) per-window spectral features, df64 inner DFT ----------------
__global__ void k_wfeat() {
    __shared__ float2 cs[32], sn[32];
    int tid = threadIdx.x;
    if (tid < 32) {
        cs[tid] = ds_from_double(cospi((double)tid / 16.0));
        sn[tid] = ds_from_double(sinpi((double)tid / 16.0));
    }
    __syncthreads();
    int wi = blockIdx.x * blockDim.x + tid;
    int b = blockIdx.y;
    if (wi >= NW_) return;
    const float4* fr4 = (const float4*)&g_aggf[b][wi * HOP_];
    float fr32[32];
#pragma unroll
    for (int q = 0; q < 8; ++q) {
        float4 v4 = __ldg(fr4 + q);
        fr32[q * 4 + 0] = v4.x; fr32[q * 4 + 1] = v4.y;
        fr32[q * 4 + 2] = v4.z; fr32[q * 4 + 3] = v4.w;
    }
    double p[16];
#pragma unroll
    for (int k = 1; k <= 16; ++k) {
        float2 re = make_float2(0.f, 0.f), im = make_float2(0.f, 0.f);
        int idx = 0;
#pragma unroll
        for (int t = 0; t < 32; ++t) {
            float v = fr32[t];
            re = ds_add(re, ds_muf(v, cs[idx]));
            im = ds_sub(im, ds_muf(v, sn[idx]));
            idx = (idx + k) & 31;
        }
        p[k - 1] = ds_to_double(ds_add(ds_mul(re, re), ds_mul(im, im)));
    }
    double tot = 0.0;
#pragma unroll
    for (int k = 0; k < 16; ++k) tot += p[k];
    double totc = fmax(tot, 1e-8);
    int dom = 1; double mv = p[0];
#pragma unroll
    for (int k = 1; k < 16; ++k) if (p[k] > mv) { mv = p[k]; dom = k + 1; }
    double wf = 0.0;
#pragma unroll
    for (int k = 0; k < 16; ++k) wf += p[k] * (double)(k + 1);
    double cent = wf / totc;
    double vs = 0.0;
#pragma unroll
    for (int k = 0; k < 16; ++k) { double d = (double)(k + 1) - cent; vs += d * d * p[k]; }
    double var = vs / totc;
    double bw = sqrt(fmax(var, 0.0)) / 32.0;
    g_feat[b][wi][0] = (double)dom / 32.0;
    g_feat[b][wi][1] = bw;
    g_feat[b][wi][2] = log1p(tot / 16.0);
}

// ---------------- 3) PELT DP, df64, EB=32 (4 groups), warp wavefront fixup -------
#define DP_SMEM ((7 * (NW_ + 1) + NWARP * EB + EB * EB + EB) * 8 + (NWARP * EB + EB) * 4 + (NW_ + 1) * 2 + 128)

__global__ __launch_bounds__(DPT, 1) void k_dp() {
    extern __shared__ char dsm[];
    float2* s_p0  = (float2*)dsm;
    float2* s_p1  = s_p0 + (NW_ + 1);
    float2* s_p2  = s_p1 + (NW_ + 1);
    float2* s_S2  = s_p2 + (NW_ + 1);
    float2* s_dp  = s_S2 + (NW_ + 1);           // scan scratch only
    float2* s_A   = s_dp + (NW_ + 1);
    float2* s_inv = s_A  + (NW_ + 1);
    float2 (*s_wv)[EB]  = (float2(*)[EB])(s_inv + (NW_ + 1));   // [NWARP][EB]
    float2 (*s_tri)[EB] = (float2(*)[EB])(s_wv + NWARP);        // [EB][EB]
    float2* s_bv = (float2*)(s_tri + EB);                       // [EB]
    int   (*s_wj)[EB] = (int(*)[EB])(s_bv + EB);                // [NWARP][EB]
    int*    s_bj = (int*)(s_wj + NWARP);                        // [EB]
    short*  s_prev = (short*)(s_bj + EB);                       // [NW+1]

    int b = blockIdx.x, tid = threadIdx.x;

    for (int i = tid; i <= NW_; i += DPT)
        s_inv[i] = ds_from_double(i ? 1.0 / (double)i : 0.0);

    // ---- df64 chunked prefix scan of feat / feat^2 (chunk = 8, 128 threads) ----
    float2 (*ch)[6] = (float2(*)[6])(void*)(s_dp + 1);   // scratch aliases s_dp[1..]
    {
        int t = tid;
        if (t < 128) {
            float2 a0 = make_float2(0, 0), a1 = a0, a2 = a0, q0 = a0, q1 = a0, q2 = a0;
            int i0 = t * 8, i1 = min(i0 + 8, NW_);
            for (int i = i0; i < i1; ++i) {
                float2 f0 = ds_from_double(g_feat[b][i][0]);
                float2 f1 = ds_from_double(g_feat[b][i][1]);
                float2 f2 = ds_from_double(g_feat[b][i][2]);
                a0 = ds_add(a0, f0); a1 = ds_add(a1, f1); a2 = ds_add(a2, f2);
                q0 = ds_add(q0, ds_mul(f0, f0));
                q1 = ds_add(q1, ds_mul(f1, f1));
                q2 = ds_add(q2, ds_mul(f2, f2));
            }
            ch[t][0] = a0; ch[t][1] = a1; ch[t][2] = a2;
            ch[t][3] = q0; ch[t][4] = q1; ch[t][5] = q2;
        }
        __syncthreads();
        if (tid == 0) {   // exclusive scan of chunk totals
            float2 r[6];
            for (int d = 0; d < 6; ++d) r[d] = make_float2(0, 0);
            for (int t2 = 0; t2 < 128; ++t2) {
                for (int d = 0; d < 6; ++d) {
                    float2 tmp = ch[t2][d];
                    ch[t2][d] = r[d];
                    r[d] = ds_add(r[d], tmp);
                }
            }
        }
        __syncthreads();
        float2 off[6];
        if (t < 128) { for (int d = 0; d < 6; ++d) off[d] = ch[t][d]; }
        __syncthreads();
        if (t < 128) {
            float2 a0 = off[0], a1 = off[1], a2 = off[2], q0 = off[3], q1 = off[4], q2 = off[5];
            int i0 = t * 8, i1 = min(i0 + 8, NW_);
            for (int i = i0; i < i1; ++i) {
                float2 f0 = ds_from_double(g_feat[b][i][0]);
                float2 f1 = ds_from_double(g_feat[b][i][1]);
                float2 f2 = ds_from_double(g_feat[b][i][2]);
                a0 = ds_add(a0, f0); a1 = ds_add(a1, f1); a2 = ds_add(a2, f2);
                q0 = ds_add(q0, ds_mul(f0, f0));
                q1 = ds_add(q1, ds_mul(f1, f1));
                q2 = ds_add(q2, ds_mul(f2, f2));
                s_p0[i + 1] = a0; s_p1[i + 1] = a1; s_p2[i + 1] = a2;
                s_S2[i + 1] = ds_add(ds_add(q0, q1), q2);
            }
        }
        if (tid == 0) {
            s_p0[0] = make_float2(0, 0); s_p1[0] = make_float2(0, 0);
            s_p2[0] = make_float2(0, 0); s_S2[0] = make_float2(0, 0);
        }
    }
    __syncthreads();
    if (tid == 0) {
        s_A[0] = ds_sub(make_float2(-1.f, 0.f), s_S2[0]);   // A[j] = dp[j] - S2[j]
    }
    __syncthreads();

    const float2 ONE = make_float2(1.f, 0.f);
    const float2 FINF = make_float2(__int_as_float(0x7f800000), 0.f);
    int lane = tid & 31, wrp = tid >> 5;

    for (int e0 = 1; e0 <= NW_; e0 += EB) {
        int kmax = min(EB, NW_ - e0 + 1);

        // ---- phase 1: argmin over j < e0 of cand' = A[j] - ss*inv, NG groups ----
#pragma unroll
        for (int g = 0; g < NG; ++g) {
            int g0 = g * EG;
            int gmax = min(EG, kmax - g0);      // uniform across threads
            if (gmax <= 0) {
                if (lane == 0) {
#pragma unroll
                    for (int k = 0; k < EG; ++k) {
                        s_wv[wrp][g0 + k] = FINF; s_wj[wrp][g0 + k] = -1;
                    }
                }
                continue;
            }
            float2 bv[EG]; int bj[EG];
#pragma unroll
            for (int k = 0; k < EG; ++k) { bv[k] = FINF; bj[k] = -1; }
            for (int j = tid; j < e0; j += DPT) {
                float2 pj0 = s_p0[j], pj1 = s_p1[j], pj2 = s_p2[j];
                float2 Aj = s_A[j];
#pragma unroll
                for (int k = 0; k < EG; ++k) {
                    if (k < gmax) {
                        int end = e0 + g0 + k;
                        float2 d0 = ds_sub(s_p0[end], pj0);
                        float2 d1 = ds_sub(s_p1[end], pj1);
                        float2 d2 = ds_sub(s_p2[end], pj2);
                        float2 ss = ds_add(ds_add(ds_mul(d0, d0), ds_mul(d1, d1)), ds_mul(d2, d2));
                        float2 cand = ds_sub(Aj, ds_mul(ss, s_inv[end - j]));
                        if (ds_lt(cand, bv[k])) { bv[k] = cand; bj[k] = j; } // ascending j: first min
                    }
                }
            }
            // warp-level argmin reduce (smallest j on ties)
#pragma unroll
            for (int k = 0; k < EG; ++k) {
                float2 v = bv[k]; int j = bj[k];
                for (int off = 16; off; off >>= 1) {
                    float2 ov;
                    ov.x = __shfl_down_sync(0xffffffffu, v.x, off);
                    ov.y = __shfl_down_sync(0xffffffffu, v.y, off);
                    int oj = __shfl_down_sync(0xffffffffu, j, off);
                    if (oj >= 0 && (j < 0 || ds_lt(ov, v) || (ov.x == v.x && ov.y == v.y && oj < j))) {
                        v = ov; j = oj;
                    }
                }
                if (lane == 0) { s_wv[wrp][g0 + k] = v; s_wj[wrp][g0 + k] = j; }
            }
        }
        // triangular SSE precompute: all 512 threads, 2 (a,k) pairs each
#pragma unroll
        for (int rep = 0; rep < 2; ++rep) {
            int idx = tid + rep * DPT;
            int a = idx & 31, k = idx >> 5;
            if (a < k && k < kmax) {
                int j = e0 + a, end = e0 + k;
                float2 d0 = ds_sub(s_p0[end], s_p0[j]);
                float2 d1 = ds_sub(s_p1[end], s_p1[j]);
                float2 d2 = ds_sub(s_p2[end], s_p2[j]);
                float2 ss = ds_add(ds_add(ds_mul(d0, d0), ds_mul(d1, d1)), ds_mul(d2, d2));
                s_tri[a][k] = ds_sub(ds_sub(s_S2[end], s_S2[j]),
                                     ds_mul(ss, s_inv[end - j]));
            }
        }
        __syncthreads();
        // cross-warp reduce: 512 threads, EB groups of NWARP(=16)
        {
            int k = tid >> 4, w = tid & 15;
            float2 v = s_wv[w][k]; int j = s_wj[w][k];
            for (int off = 8; off; off >>= 1) {
                float2 ov;
                ov.x = __shfl_down_sync(0xffffffffu, v.x, off, 16);
                ov.y = __shfl_down_sync(0xffffffffu, v.y, off, 16);
                int oj = __shfl_down_sync(0xffffffffu, j, off, 16);
                if (oj >= 0 && (j < 0 || ds_lt(ov, v) || (ov.x == v.x && ov.y == v.y && oj < j))) {
                    v = ov; j = oj;
                }
            }
            if (w == 0) { s_bv[k] = v; s_bj[k] = j; }
        }
        __syncthreads();
        // ---- phase 2: warp-parallel wavefront fixup (lanes 0..kmax-1) ----
        if (tid < 32) {
            bool act = tid < kmax;
            float2 v = FINF; int j = -1;
            if (act) {
                float2 Kk = ds_add(s_S2[e0 + tid], ONE);   // fold back Ke + penalty
                v = ds_add(s_bv[tid], Kk);
                j = s_bj[tid];
            }
#pragma unroll
            for (int a = 0; a < EB - 1; ++a) {
                float2 dpa;
                dpa.x = __shfl_sync(0xffffffffu, v.x, a);
                dpa.y = __shfl_sync(0xffffffffu, v.y, a);
                if (act && tid > a) {
                    float2 cand = ds_add(ds_add(dpa, s_tri[a][tid]), ONE);
                    if (ds_lt(cand, v)) { v = cand; j = e0 + a; }
                }
            }
            if (act) {
                int end = e0 + tid;
                s_prev[end] = (short)j;
                s_A[end] = ds_sub(v, s_S2[end]);
            }
        }
        __syncthreads();
    }

    if (tid == 0) {
        // backtrack (descending), then build ascending boundary list
        int stack[NW_ + 2];
        int cnt = 0, i = NW_;
        while (i > 0) { i = s_prev[i]; stack[cnt++] = i; }
        int nb = 0;
        g_bnd[b][nb++] = 0;
        int last = 0;
        for (int q = cnt - 2; q >= 0; --q) {     // ascending interior changepoints
            int w = stack[q];
            int t = HOP_ * w;
            if (t <= last || t - last < 8 || L_ - t < 8) continue;
            g_bnd[b][nb++] = t;
            last = t;
        }
        g_bnd[b][nb] = L_;
        g_nseg[b] = nb;
        int acc = 0, bacc = 0;
        for (int si = 0; si < nb; ++si) {
            int n = g_bnd[b][si + 1] - g_bnd[b][si];
            g_boff[b][si] = acc;   acc += n >> 1;
            int blkn;
            if ((n & 15) == 0) { int ncls = (n >> 5) + 1; blkn = (ncls + 7) >> 3; }
            else               { int ncls = (n >> 4) + 1; blkn = (ncls + 15) >> 4; }
            g_blkoff[b][si] = bacc; bacc += blkn;
        }
        g_boff[b][nb] = acc;
        g_blkoff[b][nb] = bacc;
    }
}

// ---------------- 4) segment spectra: dual-radix time-chunked Goertzel -----------
// n%16==0: D=16 path — 8 classes x (8 chunks x 2 phase-halves) per 128-thr block.
// n%16==8: D=8 path  — 16 classes x 8 chunks (as R10).
__global__ __launch_bounds__(128) void k_dft() {
    int blk = blockIdx.x, b = blockIdx.y;
    int ns = g_nseg[b];
    if (blk >= g_blkoff[b][ns]) return;
    int lo = 0, hi = ns;
    while (hi - lo > 1) { int mid = (lo + hi) >> 1; if (g_blkoff[b][mid] <= blk) lo = mid; else hi = mid; }
    int si = lo;
    int s = g_bnd[b][si], e = g_bnd[b][si + 1], n = e - s;
    int tid = threadIdx.x;
    const float4* xs = (const float4*)&g_aggf[b][s];   // s multiple of 8 -> 32B aligned
    double dn = (double)n;
    int half = n >> 1;
    double* pw = &g_pw[b][g_boff[b][si]];

    if ((n & 15) == 0) {
        // ================= D = 16 path =================
        int m16 = n >> 4;
        int ncls = (n >> 5) + 1;
        int qtile = blk - g_blkoff[b][si];
        int ql = tid >> 4;          // 8 classes per block
        int sub = tid & 15;
        int c = sub >> 1, h = sub & 1;
        int q = qtile * 8 + ql;
        bool act = q < ncls;
        int k0 = act ? ((q == 0) ? m16 : q) : 1;
        double swd, cwd;
        sincospi(32.0 * (double)k0 / dn, &swd, &cwd);   // omega = 2*pi*16*k0/n
        float2 coeff = ds_from_double(2.0 * cwd);
        float2 s1[8], s2[8];
#pragma unroll
        for (int ph = 0; ph < 8; ++ph) { s1[ph] = make_float2(0, 0); s2[ph] = make_float2(0, 0); }
        int M = n >> 4;             // stream length per phase
        int Mc = (M + 7) >> 3;
        int t0 = c * Mc, t1 = min(M, t0 + Mc);
        for (int tau = t0; tau < t1; ++tau) {
            float4 va = __ldg(xs + tau * 4 + 2 * h);
            float4 vb = __ldg(xs + tau * 4 + 2 * h + 1);
            float v[8] = {va.x, va.y, va.z, va.w, vb.x, vb.y, vb.z, vb.w};
#pragma unroll
            for (int ph = 0; ph < 8; ++ph) {
                float2 tq = s1[ph];
                s1[ph] = ds_add(ds_mul(coeff, tq), ds_fsub(v[ph], s2[ph]));
                s2[ph] = tq;
            }
        }
        // finalize + de-rotate chunk by e^{-i w (t1-1)}
        double zr[8], zi[8];
        {
            double rs, rc;
            sincospi(32.0 * (double)k0 * (double)(t1 > 0 ? t1 - 1 : 0) / dn, &rs, &rc);
#pragma unroll
            for (int ph = 0; ph < 8; ++ph) {
                double S1 = ds_to_double(s1[ph]), S2d = ds_to_double(s2[ph]);
                double ar = S1 - cwd * S2d;
                double ai = swd * S2d;
                zr[ph] = rc * ar + rs * ai;
                zi[ph] = rc * ai - rs * ar;
            }
        }
        // chunk-sum over c (same h): stride-2 offsets within width-16 groups
#pragma unroll
        for (int off = 8; off >= 2; off >>= 1) {
#pragma unroll
            for (int ph = 0; ph < 8; ++ph) {
                zr[ph] += __shfl_down_sync(0xffffffffu, zr[ph], off, 16);
                zi[ph] += __shfl_down_sync(0xffffffffu, zi[ph], off, 16);
            }
        }
        // lanes sub==0 (phases 0-7) and sub==1 (phases 8-15) hold the class sums.
        bool selfm = (2 * q == m16);
        // q-side bins: k = q + j*m16
#pragma unroll
        for (int j = 0; j <= 8; ++j) {
            int k = q + j * m16;
            bool valid = act && k >= 1 && k <= half;
            double c1, s1r;
            sincospi(2.0 * (double)k / dn, &s1r, &c1);
            double cp, sp;
            if (h) { sincospi(16.0 * (double)k / dn, &sp, &cp); } else { cp = 1.0; sp = 0.0; }
            double ar = 0.0, ai = 0.0;
#pragma unroll
            for (int ph = 0; ph < 8; ++ph) {
                ar += cp * zr[ph] + sp * zi[ph];
                ai += cp * zi[ph] - sp * zr[ph];
                double ncp = cp * c1 - sp * s1r;
                sp = sp * c1 + cp * s1r;
                cp = ncp;
            }
            double ar1 = __shfl_down_sync(0xffffffffu, ar, 1, 16);
            double ai1 = __shfl_down_sync(0xffffffffu, ai, 1, 16);
            if (sub == 0 && valid) {
                double AR = ar + ar1, AI = ai + ai1;
                pw[k - 1] = AR * AR + AI * AI;
            }
        }
        // mirror-side bins: k = j*m16 - q  (zi flips sign)
#pragma unroll
        for (int j = 1; j <= 8; ++j) {
            int k = j * m16 - q;
            bool valid = act && q > 0 && !selfm && k >= 1 && k <= half;
            double c1, s1r;
            sincospi(2.0 * (double)k / dn, &s1r, &c1);
            double cp, sp;
            if (h) { sincospi(16.0 * (double)k / dn, &sp, &cp); } else { cp = 1.0; sp = 0.0; }
            double ar = 0.0, ai = 0.0;
#pragma unroll
            for (int ph = 0; ph < 8; ++ph) {
                double zrm = zr[ph], zim = -zi[ph];
                ar += cp * zrm + sp * zim;
                ai += cp * zim - sp * zrm;
                double ncp = cp * c1 - sp * s1r;
                sp = sp * c1 + cp * s1r;
                cp = ncp;
            }
            double ar1 = __shfl_down_sync(0xffffffffu, ar, 1, 16);
            double ai1 = __shfl_down_sync(0xffffffffu, ai, 1, 16);
            if (sub == 0 && valid) {
                double AR = ar + ar1, AI = ai + ai1;
                pw[k - 1] = AR * AR + AI * AI;
            }
        }
    } else {
        // ================= D = 8 path (n % 16 == 8) =================
        int m8 = n >> 3;
        int ncls = (n >> 4) + 1;
        int qtile = blk - g_blkoff[b][si];
        int ql = tid >> 3, c = tid & 7;
        int q = qtile * 16 + ql;
        bool act = q < ncls;
        int k0 = act ? ((q == 0) ? m8 : q) : 1;
        double swd, cwd;
        sincospi(16.0 * (double)k0 / dn, &swd, &cwd);   // omega = 2*pi*8*k0/n
        float2 coeff = ds_from_double(2.0 * cwd);
        float2 s1[8], s2[8];
#pragma unroll
        for (int ph = 0; ph < 8; ++ph) { s1[ph] = make_float2(0, 0); s2[ph] = make_float2(0, 0); }
        int M = n >> 3;
        int Mc = (M + 7) >> 3;
        int t0 = c * Mc, t1 = min(M, t0 + Mc);
        for (int tau = t0; tau < t1; ++tau) {
            float4 va = __ldg(xs + tau * 2);
            float4 vb = __ldg(xs + tau * 2 + 1);
            float v[8] = {va.x, va.y, va.z, va.w, vb.x, vb.y, vb.z, vb.w};
#pragma unroll
            for (int ph = 0; ph < 8; ++ph) {
                float2 tq = s1[ph];
                s1[ph] = ds_add(ds_mul(coeff, tq), ds_fsub(v[ph], s2[ph]));
                s2[ph] = tq;
            }
        }
        double zr[8], zi[8];
        {
            double rs, rc;
            sincospi(16.0 * (double)k0 * (double)(t1 > 0 ? t1 - 1 : 0) / dn, &rs, &rc);
#pragma unroll
            for (int ph = 0; ph < 8; ++ph) {
                double S1 = ds_to_double(s1[ph]), S2d = ds_to_double(s2[ph]);
                double ar = S1 - cwd * S2d;
                double ai = swd * S2d;
                zr[ph] = rc * ar + rs * ai;
                zi[ph] = rc * ai - rs * ar;
            }
        }
#pragma unroll
        for (int off = 4; off; off >>= 1) {
#pragma unroll
            for (int ph = 0; ph < 8; ++ph) {
                zr[ph] += __shfl_down_sync(0xffffffffu, zr[ph], off, 8);
                zi[ph] += __shfl_down_sync(0xffffffffu, zi[ph], off, 8);
            }
        }
        if (c != 0 || !act) return;
#pragma unroll
        for (int j = 0; j <= 4; ++j) {
            int k = q + j * m8;
            if (k < 1 || k > half) continue;
            double c1, s1r;
            sincospi(2.0 * (double)k / dn, &s1r, &c1);
            double cp = 1.0, sp = 0.0, ar = 0.0, ai = 0.0;
#pragma unroll
            for (int ph = 0; ph < 8; ++ph) {
                ar += cp * zr[ph] + sp * zi[ph];
                ai += cp * zi[ph] - sp * zr[ph];
                double ncp = cp * c1 - sp * s1r;
                sp = sp * c1 + cp * s1r;
                cp = ncp;
            }
            pw[k - 1] = ar * ar + ai * ai;
        }
        if (q > 0 && 2 * q != m8) {
#pragma unroll
            for (int j = 1; j <= 4; ++j) {
                int k = j * m8 - q;
                if (k < 1 || k > half) continue;
                double c1, s1r;
                sincospi(2.0 * (double)k / dn, &s1r, &c1);
                double cp = 1.0, sp = 0.0, ar = 0.0, ai = 0.0;
#pragma unroll
                for (int ph = 0; ph < 8; ++ph) {
                    double zrm = zr[ph], zim = -zi[ph];
                    ar += cp * zrm + sp * zim;
                    ai += cp * zim - sp * zrm;
                    double ncp = cp * c1 - sp * s1r;
                    sp = sp * c1 + cp * s1r;
                    cp = ncp;
                }
                pw[k - 1] = ar * ar + ai * ai;
            }
        }
    }
}

// ---------------- 5) per-segment stats + patch length ----------------------------
__global__ __launch_bounds__(256) void k_segstats() {
    int si = blockIdx.x, b = blockIdx.y;
    if (si >= g_nseg[b]) return;
    int s = g_bnd[b][si], e = g_bnd[b][si + 1], n = e - s, m = n >> 1;
    const double* p = &g_pw[b][g_boff[b][si]];
    __shared__ double rs[256], rw[256], rmv[256];
    __shared__ int rmi[256];
    __shared__ double sh_cent, sh_tot;
    int tid = threadIdx.x;
    double tot = 0.0, wf = 0.0, mv = -1.0; int mi = 0x7fffffff;
    for (int kk = tid; kk < m; kk += 256) {
        double pv = p[kk];
        tot += pv; wf += pv * (double)(kk + 1);
        if (pv > mv) { mv = pv; mi = kk; }
    }
    rs[tid] = tot; rw[tid] = wf; rmv[tid] = mv; rmi[tid] = mi;
    __syncthreads();
    for (int off = 128; off; off >>= 1) {
        if (tid < off) {
            rs[tid] += rs[tid + off];
            rw[tid] += rw[tid + off];
            if (rmv[tid + off] > rmv[tid] ||
                (rmv[tid + off] == rmv[tid] && rmi[tid + off] < rmi[tid])) {
                rmv[tid] = rmv[tid + off]; rmi[tid] = rmi[tid + off];
            }
        }
        __syncthreads();
    }
    if (tid == 0) { sh_tot = fmax(rs[0], 1e-8); sh_cent = rw[0] / sh_tot; }
    __syncthreads();
    double cent = sh_cent;
    double vs = 0.0;
    for (int kk = tid; kk < m; kk += 256) {
        double d = (double)(kk + 1) - cent;
        vs += d * d * p[kk];
    }
    __syncthreads();
    rs[tid] = vs;
    __syncthreads();
    for (int off = 128; off; off >>= 1) {
        if (tid < off) rs[tid] += rs[tid + off];
        __syncthreads();
    }
    if (tid == 0) {
        double var = rs[0] / sh_tot;
        double bw = sqrt(fmax(var, 0.0)) / (double)n;
        int dom = rmi[0] + 1;
        double dom_p = (double)n / (double)dom;
        double raw = dom_p / (1.0 + bw);
        int pl = (int)rint(raw * 0.5) * 2;      // round-half-even like numpy
        pl = min(max(pl, 8), 64);
        g_sdom[b][si] = dom_p;
        g_sbw[b][si] = bw;
        g_spl[b][si] = pl;
        g_snp[b][si] = (n + pl - 1) / pl;
    }
}

// ---------------- 6) per-batch token-offset scan + n_tokens out ------------------
__global__ void k_scantok(float* o_ntok) {
    int b = threadIdx.x;
    if (b >= B_) return;
    int ns = g_nseg[b], acc = 0;
    for (int si = 0; si < ns; ++si) { g_toff[b][si] = acc; acc += g_snp[b][si]; }
    g_toff[b][ns] = acc;
    g_ntok[b] = acc;
    o_ntok[b] = (float)acc;
}

// ---------------- 7) token metadata (+ compact token table) -----------------------
__global__ void k_meta(float* o_mask, float* o_start, float* o_end, float* o_center,
                       float* o_span, float* o_regime, int mx) {
    int t = blockIdx.x * blockDim.x + threadIdx.x;
    int b = blockIdx.y;
    if (t >= mx) return;
    int nt = g_ntok[b];
    int ns = g_nseg[b];
    size_t o = (size_t)b * mx + t;
    float mask = 0.f, fs = 0.f, fe = 0.f, fc = 0.f, fp = 0.f, r0 = 0.f, r1 = 0.f, r2 = 0.f;
    if (t < nt && t < MAXTOK_) {
        int lo = 0, hi = ns;
        while (hi - lo > 1) { int mid = (lo + hi) >> 1; if (g_toff[b][mid] <= t) lo = mid; else hi = mid; }
        int si = lo;
        int pi = t - g_toff[b][si];
        int s = g_bnd[b][si], e = g_bnd[b][si + 1];
        int pl = g_spl[b][si];
        int a = s + pi * pl;
        int z = min(e, a + pl);
        g_tok[b][t][0] = a; g_tok[b][t][1] = z;
        mask = 1.f;
        fs = (float)a; fe = (float)z;
        fc = (float)((double)(a + z - 1) * 0.5 / (double)(L_ - 1));
        fp = (float)((double)(z - a) / (double)L_);
        r0 = (float)(g_sdom[b][si] / (double)L_);
        r1 = (float)g_sbw[b][si];
        r2 = (float)((double)(e - s) / (double)L_);
    } else if (t < MAXTOK_) {
        g_tok[b][t][0] = 0; g_tok[b][t][1] = 0;
    }
    o_mask[o] = mask; o_start[o] = fs; o_end[o] = fe;
    o_center[o] = fc; o_span[o] = fp;
    o_regime[o * 3 + 0] = r0; o_regime[o * 3 + 1] = r1; o_regime[o * 3 + 2] = r2;
}

// ---------------- 8) patch gather (resize to 16 anchors) --------------------------
__global__ __launch_bounds__(256) void k_patch(const float* __restrict__ x,
                                               float* __restrict__ o_pat, int mx) {
    int t = blockIdx.x, b = blockIdx.y, tid = threadIdx.x;
    float* outp = o_pat + ((size_t)b * mx + t) * (C_ * 16);
    int nt = min(g_ntok[b], MAXTOK_);
    if (t >= nt) {
        for (int i = tid; i < C_ * 16; i += 256) outp[i] = 0.f;
        return;
    }
    int a = g_tok[b][t][0], z = g_tok[b][t][1];
    int n = z - a;
    double q = (double)n / 16.0;
    const float* xb = x + (size_t)b * C_ * L_;
    for (int i = tid; i < C_ * 16; i += 256) {
        int c = i >> 4, j = i & 15;
        double src = ((double)j + 0.5) * q - 0.5;
        src = fmin(fmax(src, 0.0), (double)(n - 1));
        int i0 = (int)floor(src);
        int i1 = min(i0 + 1, n - 1);
        float w = (float)(src - (double)i0);
        float x0 = xb[(size_t)c * L_ + a + i0];
        float x1 = xb[(size_t)c * L_ + a + i1];
        outp[i] = x0 * (1.0f - w) + x1 * w;
    }
}

// ---------------- host launcher ---------------------------------------------------
extern "C" void kernel_launch(void* const* d_in, const int* in_sizes, int n_in,
                              void* d_out, int out_size) {
    const float* x = (const float*)d_in[0];
    float* out = (float*)d_out;

    // out_size = 32*(1032*mx + 1): patches(32*mx*1024) + 5*(32*mx) + regime(32*mx*3) + 32
    long long mx = ((long long)out_size / 32 - 1) / 1032;
    if (mx < 1) mx = 1;

    float* o_pat    = out;
    float* o_mask   = o_pat + (size_t)B_ * mx * (C_ * 16);
    float* o_start  = o_mask + (size_t)B_ * mx;
    float* o_end    = o_start + (size_t)B_ * mx;
    float* o_center = o_end + (size_t)B_ * mx;
    float* o_span   = o_center + (size_t)B_ * mx;
    float* o_regime = o_span + (size_t)B_ * mx;
    float* o_ntok   = o_regime + (size_t)B_ * mx * 3;

    cudaFuncSetAttribute(k_dp, cudaFuncAttributeMaxDynamicSharedMemorySize, DP_SMEM);

    k_agg<<<dim3(L_ / 256, B_), 256>>>(x);
    k_wfeat<<<dim3((NW_ + 127) / 128, B_), 128>>>();
    k_dp<<<B_, DPT, DP_SMEM>>>();
    k_dft<<<dim3(BCAP_, B_), 128>>>();           // slot 4 -> gets profiled
    k_segstats<<<dim3(MAXSEG_, B_), 256>>>();
    k_scantok<<<1, 32>>>(o_ntok);
    k_meta<<<dim3((unsigned)((mx + 255) / 256), B_), 256>>>(o_mask, o_start, o_end,
                                                            o_center, o_span, o_regime, (int)mx);
    k_patch<<<dim3((unsigned)mx, B_), 256>>>(x, o_pat, (int)mx);
}

// round 12
// speedup vs baseline: 1.1307x; 1.1307x over previous
#include <cuda_runtime.h>
#include <math.h>

#define B_ 32
#define C_ 64
#define L_ 8192
#define W_ 32
#define HOP_ 8
#define NW_ 1021          // (8192-32)/8 + 1 ; last start == L-W so no append
#define NBINS_ 4096       // total spectral bins per batch (sum n_i/2 == L/2)
#define BCAP_ 1152        // dft block capacity per batch
#define MAXSEG_ 1025
#define MAXTOK_ 2048
#define EB 32             // DP end-batch size
#define EG 8              // DP sub-group size (register working set)
#define NG (EB / EG)      // sub-groups per round
#define DPT 512           // DP threads per block
#define NWARP (DPT / 32)

// ================= double-single (df64) arithmetic, fast-math-proof =============
__device__ __forceinline__ float2 ds_from_double(double d) {
    float h = (float)d;
    return make_float2(h, (float)(d - (double)h));
}
__device__ __forceinline__ double ds_to_double(float2 a) {
    return (double)a.x + (double)a.y;
}
__device__ __forceinline__ float2 ds_add(float2 a, float2 b) {
    float s = __fadd_rn(a.x, b.x);
    float v = __fadd_rn(s, -a.x);
    float e = __fadd_rn(__fadd_rn(a.x, -__fadd_rn(s, -v)),
                        __fadd_rn(b.x, -v));
    e = __fadd_rn(e, __fadd_rn(a.y, b.y));
    float hi = __fadd_rn(s, e);
    float lo = __fadd_rn(e, -__fadd_rn(hi, -s));
    return make_float2(hi, lo);
}
__device__ __forceinline__ float2 ds_neg(float2 a) { return make_float2(-a.x, -a.y); }
__device__ __forceinline__ float2 ds_sub(float2 a, float2 b) { return ds_add(a, ds_neg(b)); }
// (a,0) - b  : exact-float minus df64
__device__ __forceinline__ float2 ds_fsub(float a, float2 b) {
    float bx = -b.x;
    float s = __fadd_rn(a, bx);
    float v = __fadd_rn(s, -a);
    float e = __fadd_rn(__fadd_rn(a, -__fadd_rn(s, -v)),
                        __fadd_rn(bx, -v));
    e = __fadd_rn(e, -b.y);
    float hi = __fadd_rn(s, e);
    float lo = __fadd_rn(e, -__fadd_rn(hi, -s));
    return make_float2(hi, lo);
}
__device__ __forceinline__ float2 ds_mul(float2 a, float2 b) {
    float p = __fmul_rn(a.x, b.x);
    float e = __fmaf_rn(a.x, b.x, -p);
    e = __fmaf_rn(a.x, b.y, e);
    e = __fmaf_rn(a.y, b.x, e);
    float hi = __fadd_rn(p, e);
    float lo = __fadd_rn(e, -__fadd_rn(hi, -p));
    return make_float2(hi, lo);
}
__device__ __forceinline__ float2 ds_muf(float a, float2 b) {   // exact-float * df64
    float p = __fmul_rn(a, b.x);
    float e = __fmaf_rn(a, b.x, -p);
    e = __fmaf_rn(a, b.y, e);
    float hi = __fadd_rn(p, e);
    float lo = __fadd_rn(e, -__fadd_rn(hi, -p));
    return make_float2(hi, lo);
}
__device__ __forceinline__ bool ds_lt(float2 a, float2 b) {
    return (a.x < b.x) || (a.x == b.x && a.y < b.y);
}

// ---------------- device scratch (static: no allocation allowed) ----------------
__device__ float  g_aggf[B_][L_];
__device__ double g_feat[B_][NW_][3];
__device__ int    g_bnd[B_][MAXSEG_ + 1];
__device__ int    g_nseg[B_];
__device__ int    g_boff[B_][MAXSEG_ + 1];
__device__ int    g_blkoff[B_][MAXSEG_ + 1];
__device__ double g_pw[B_][NBINS_];
__device__ double g_sdom[B_][MAXSEG_];
__device__ double g_sbw[B_][MAXSEG_];
__device__ int    g_spl[B_][MAXSEG_];
__device__ int    g_snp[B_][MAXSEG_];
__device__ int    g_toff[B_][MAXSEG_ + 1];
__device__ int    g_ntok[B_];
__device__ int    g_tok[B_][MAXTOK_][2];

// ---------------- 1) channel mean (fp32 sequential like numpy; exact in fp32) ----
__global__ void k_agg(const float* __restrict__ x) {
    int t = blockIdx.x * blockDim.x + threadIdx.x;
    int b = blockIdx.y;
    if (t >= L_) return;
    const float* xp = x + (size_t)b * C_ * L_ + t;
    float s = 0.0f;
#pragma unroll 8
    for (int c = 0; c < C_; ++c) s += xp[(size_t)c * L_];
    g_aggf[b][t] = s * (1.0f / 64.0f);
}

// ---------------- 2) per-window spectral features, df64 inner DFT ----------------
__global__ void k_wfeat() {
    __shared__ float2 cs[32], sn[32];
    int tid = threadIdx.x;
    if (tid < 32) {
        cs[tid] = ds_from_double(cospi((double)tid / 16.0));
        sn[tid] = ds_from_double(sinpi((double)tid / 16.0));
    }
    __syncthreads();
    int wi = blockIdx.x * blockDim.x + tid;
    int b = blockIdx.y;
    if (wi >= NW_) return;
    const float4* fr4 = (const float4*)&g_aggf[b][wi * HOP_];
    float fr32[32];
#pragma unroll
    for (int q = 0; q < 8; ++q) {
        float4 v4 = __ldg(fr4 + q);
        fr32[q * 4 + 0] = v4.x; fr32[q * 4 + 1] = v4.y;
        fr32[q * 4 + 2] = v4.z; fr32[q * 4 + 3] = v4.w;
    }
    double p[16];
#pragma unroll
    for (int k = 1; k <= 16; ++k) {
        float2 re = make_float2(0.f, 0.f), im = make_float2(0.f, 0.f);
        int idx = 0;
#pragma unroll
        for (int t = 0; t < 32; ++t) {
            float v = fr32[t];
            re = ds_add(re, ds_muf(v, cs[idx]));
            im = ds_sub(im, ds_muf(v, sn[idx]));
            idx = (idx + k) & 31;
        }
        p[k - 1] = ds_to_double(ds_add(ds_mul(re, re), ds_mul(im, im)));
    }
    double tot = 0.0;
#pragma unroll
    for (int k = 0; k < 16; ++k) tot += p[k];
    double totc = fmax(tot, 1e-8);
    int dom = 1; double mv = p[0];
#pragma unroll
    for (int k = 1; k < 16; ++k) if (p[k] > mv) { mv = p[k]; dom = k + 1; }
    double wf = 0.0;
#pragma unroll
    for (int k = 0; k < 16; ++k) wf += p[k] * (double)(k + 1);
    double cent = wf / totc;
    double vs = 0.0;
#pragma unroll
    for (int k = 0; k < 16; ++k) { double d = (double)(k + 1) - cent; vs += d * d * p[k]; }
    double var = vs / totc;
    double bw = sqrt(fmax(var, 0.0)) / 32.0;
    g_feat[b][wi][0] = (double)dom / 32.0;
    g_feat[b][wi][1] = bw;
    g_feat[b][wi][2] = log1p(tot / 16.0);
}

// ---------------- 3) PELT DP, df64, EB=32 (4 groups), warp wavefront fixup -------
#define DP_SMEM ((7 * (NW_ + 1) + NWARP * EB + EB * EB + EB) * 8 + (NWARP * EB + EB) * 4 + (NW_ + 1) * 2 + 128)

__global__ __launch_bounds__(DPT, 1) void k_dp() {
    extern __shared__ char dsm[];
    float2* s_p0  = (float2*)dsm;
    float2* s_p1  = s_p0 + (NW_ + 1);
    float2* s_p2  = s_p1 + (NW_ + 1);
    float2* s_S2  = s_p2 + (NW_ + 1);
    float2* s_dp  = s_S2 + (NW_ + 1);           // scan scratch only
    float2* s_A   = s_dp + (NW_ + 1);
    float2* s_inv = s_A  + (NW_ + 1);
    float2 (*s_wv)[EB]  = (float2(*)[EB])(s_inv + (NW_ + 1));   // [NWARP][EB]
    float2 (*s_tri)[EB] = (float2(*)[EB])(s_wv + NWARP);        // [EB][EB]
    float2* s_bv = (float2*)(s_tri + EB);                       // [EB]
    int   (*s_wj)[EB] = (int(*)[EB])(s_bv + EB);                // [NWARP][EB]
    int*    s_bj = (int*)(s_wj + NWARP);                        // [EB]
    short*  s_prev = (short*)(s_bj + EB);                       // [NW+1]

    int b = blockIdx.x, tid = threadIdx.x;

    for (int i = tid; i <= NW_; i += DPT)
        s_inv[i] = ds_from_double(i ? 1.0 / (double)i : 0.0);

    // ---- df64 chunked prefix scan of feat / feat^2 (chunk = 8, 128 threads) ----
    float2 (*ch)[6] = (float2(*)[6])(void*)(s_dp + 1);   // scratch aliases s_dp[1..]
    {
        int t = tid;
        if (t < 128) {
            float2 a0 = make_float2(0, 0), a1 = a0, a2 = a0, q0 = a0, q1 = a0, q2 = a0;
            int i0 = t * 8, i1 = min(i0 + 8, NW_);
            for (int i = i0; i < i1; ++i) {
                float2 f0 = ds_from_double(g_feat[b][i][0]);
                float2 f1 = ds_from_double(g_feat[b][i][1]);
                float2 f2 = ds_from_double(g_feat[b][i][2]);
                a0 = ds_add(a0, f0); a1 = ds_add(a1, f1); a2 = ds_add(a2, f2);
                q0 = ds_add(q0, ds_mul(f0, f0));
                q1 = ds_add(q1, ds_mul(f1, f1));
                q2 = ds_add(q2, ds_mul(f2, f2));
            }
            ch[t][0] = a0; ch[t][1] = a1; ch[t][2] = a2;
            ch[t][3] = q0; ch[t][4] = q1; ch[t][5] = q2;
        }
        __syncthreads();
        if (tid == 0) {   // exclusive scan of chunk totals
            float2 r[6];
            for (int d = 0; d < 6; ++d) r[d] = make_float2(0, 0);
            for (int t2 = 0; t2 < 128; ++t2) {
                for (int d = 0; d < 6; ++d) {
                    float2 tmp = ch[t2][d];
                    ch[t2][d] = r[d];
                    r[d] = ds_add(r[d], tmp);
                }
            }
        }
        __syncthreads();
        float2 off[6];
        if (t < 128) { for (int d = 0; d < 6; ++d) off[d] = ch[t][d]; }
        __syncthreads();
        if (t < 128) {
            float2 a0 = off[0], a1 = off[1], a2 = off[2], q0 = off[3], q1 = off[4], q2 = off[5];
            int i0 = t * 8, i1 = min(i0 + 8, NW_);
            for (int i = i0; i < i1; ++i) {
                float2 f0 = ds_from_double(g_feat[b][i][0]);
                float2 f1 = ds_from_double(g_feat[b][i][1]);
                float2 f2 = ds_from_double(g_feat[b][i][2]);
                a0 = ds_add(a0, f0); a1 = ds_add(a1, f1); a2 = ds_add(a2, f2);
                q0 = ds_add(q0, ds_mul(f0, f0));
                q1 = ds_add(q1, ds_mul(f1, f1));
                q2 = ds_add(q2, ds_mul(f2, f2));
                s_p0[i + 1] = a0; s_p1[i + 1] = a1; s_p2[i + 1] = a2;
                s_S2[i + 1] = ds_add(ds_add(q0, q1), q2);
            }
        }
        if (tid == 0) {
            s_p0[0] = make_float2(0, 0); s_p1[0] = make_float2(0, 0);
            s_p2[0] = make_float2(0, 0); s_S2[0] = make_float2(0, 0);
        }
    }
    __syncthreads();
    if (tid == 0) {
        s_A[0] = ds_sub(make_float2(-1.f, 0.f), s_S2[0]);   // A[j] = dp[j] - S2[j]
    }
    __syncthreads();

    const float2 ONE = make_float2(1.f, 0.f);
    const float2 FINF = make_float2(__int_as_float(0x7f800000), 0.f);
    int lane = tid & 31, wrp = tid >> 5;

    for (int e0 = 1; e0 <= NW_; e0 += EB) {
        int kmax = min(EB, NW_ - e0 + 1);

        // ---- phase 1: argmin over j < e0 of cand' = A[j] - ss*inv, NG groups ----
#pragma unroll
        for (int g = 0; g < NG; ++g) {
            int g0 = g * EG;
            int gmax = min(EG, kmax - g0);      // uniform across threads
            if (gmax <= 0) {
                if (lane == 0) {
#pragma unroll
                    for (int k = 0; k < EG; ++k) {
                        s_wv[wrp][g0 + k] = FINF; s_wj[wrp][g0 + k] = -1;
                    }
                }
                continue;
            }
            float2 bv[EG]; int bj[EG];
#pragma unroll
            for (int k = 0; k < EG; ++k) { bv[k] = FINF; bj[k] = -1; }
            for (int j = tid; j < e0; j += DPT) {
                float2 pj0 = s_p0[j], pj1 = s_p1[j], pj2 = s_p2[j];
                float2 Aj = s_A[j];
#pragma unroll
                for (int k = 0; k < EG; ++k) {
                    if (k < gmax) {
                        int end = e0 + g0 + k;
                        float2 d0 = ds_sub(s_p0[end], pj0);
                        float2 d1 = ds_sub(s_p1[end], pj1);
                        float2 d2 = ds_sub(s_p2[end], pj2);
                        float2 ss = ds_add(ds_add(ds_mul(d0, d0), ds_mul(d1, d1)), ds_mul(d2, d2));
                        float2 cand = ds_sub(Aj, ds_mul(ss, s_inv[end - j]));
                        if (ds_lt(cand, bv[k])) { bv[k] = cand; bj[k] = j; } // ascending j: first min
                    }
                }
            }
            // warp-level argmin reduce (smallest j on ties)
#pragma unroll
            for (int k = 0; k < EG; ++k) {
                float2 v = bv[k]; int j = bj[k];
                for (int off = 16; off; off >>= 1) {
                    float2 ov;
                    ov.x = __shfl_down_sync(0xffffffffu, v.x, off);
                    ov.y = __shfl_down_sync(0xffffffffu, v.y, off);
                    int oj = __shfl_down_sync(0xffffffffu, j, off);
                    if (oj >= 0 && (j < 0 || ds_lt(ov, v) || (ov.x == v.x && ov.y == v.y && oj < j))) {
                        v = ov; j = oj;
                    }
                }
                if (lane == 0) { s_wv[wrp][g0 + k] = v; s_wj[wrp][g0 + k] = j; }
            }
        }
        // triangular SSE precompute: all 512 threads, 2 (a,k) pairs each
#pragma unroll
        for (int rep = 0; rep < 2; ++rep) {
            int idx = tid + rep * DPT;
            int a = idx & 31, k = idx >> 5;
            if (a < k && k < kmax) {
                int j = e0 + a, end = e0 + k;
                float2 d0 = ds_sub(s_p0[end], s_p0[j]);
                float2 d1 = ds_sub(s_p1[end], s_p1[j]);
                float2 d2 = ds_sub(s_p2[end], s_p2[j]);
                float2 ss = ds_add(ds_add(ds_mul(d0, d0), ds_mul(d1, d1)), ds_mul(d2, d2));
                s_tri[a][k] = ds_sub(ds_sub(s_S2[end], s_S2[j]),
                                     ds_mul(ss, s_inv[end - j]));
            }
        }
        __syncthreads();
        // cross-warp reduce: 512 threads, EB groups of NWARP(=16)
        {
            int k = tid >> 4, w = tid & 15;
            float2 v = s_wv[w][k]; int j = s_wj[w][k];
            for (int off = 8; off; off >>= 1) {
                float2 ov;
                ov.x = __shfl_down_sync(0xffffffffu, v.x, off, 16);
                ov.y = __shfl_down_sync(0xffffffffu, v.y, off, 16);
                int oj = __shfl_down_sync(0xffffffffu, j, off, 16);
                if (oj >= 0 && (j < 0 || ds_lt(ov, v) || (ov.x == v.x && ov.y == v.y && oj < j))) {
                    v = ov; j = oj;
                }
            }
            if (w == 0) { s_bv[k] = v; s_bj[k] = j; }
        }
        __syncthreads();
        // ---- phase 2: warp-parallel wavefront fixup (lanes 0..kmax-1) ----
        if (tid < 32) {
            bool act = tid < kmax;
            float2 v = FINF; int j = -1;
            if (act) {
                float2 Kk = ds_add(s_S2[e0 + tid], ONE);   // fold back Ke + penalty
                v = ds_add(s_bv[tid], Kk);
                j = s_bj[tid];
            }
#pragma unroll
            for (int a = 0; a < EB - 1; ++a) {
                float2 dpa;
                dpa.x = __shfl_sync(0xffffffffu, v.x, a);
                dpa.y = __shfl_sync(0xffffffffu, v.y, a);
                if (act && tid > a) {
                    float2 cand = ds_add(ds_add(dpa, s_tri[a][tid]), ONE);
                    if (ds_lt(cand, v)) { v = cand; j = e0 + a; }
                }
            }
            if (act) {
                int end = e0 + tid;
                s_prev[end] = (short)j;
                s_A[end] = ds_sub(v, s_S2[end]);
            }
        }
        __syncthreads();
    }

    if (tid == 0) {
        // backtrack (descending), then build ascending boundary list
        int stack[NW_ + 2];
        int cnt = 0, i = NW_;
        while (i > 0) { i = s_prev[i]; stack[cnt++] = i; }
        int nb = 0;
        g_bnd[b][nb++] = 0;
        int last = 0;
        for (int q = cnt - 2; q >= 0; --q) {     // ascending interior changepoints
            int w = stack[q];
            int t = HOP_ * w;
            if (t <= last || t - last < 8 || L_ - t < 8) continue;
            g_bnd[b][nb++] = t;
            last = t;
        }
        g_bnd[b][nb] = L_;
        g_nseg[b] = nb;
        int acc = 0, bacc = 0;
        for (int si = 0; si < nb; ++si) {
            int n = g_bnd[b][si + 1] - g_bnd[b][si];
            g_boff[b][si] = acc;   acc += n >> 1;
            int ncls = (n >> 4) + 1;
            g_blkoff[b][si] = bacc; bacc += (ncls + 7) >> 3;   // 8 classes per block
        }
        g_boff[b][nb] = acc;
        g_blkoff[b][nb] = bacc;
    }
}

// ---------------- 4) segment spectra: D=8 Goertzel, 8 classes x 16 chunks --------
// One block per (segment, 8-class tile). blockDim 128 = 8 classes x 16 chunks.
// Each chunk runs the decimated recurrence on its tau-slice, de-rotates by
// e^{-i w (t1-1)}, then a width-16 shuffle tree sums chunks; lane c=0 emits bins.
__global__ __launch_bounds__(128) void k_dft() {
    int blk = blockIdx.x, b = blockIdx.y;
    int ns = g_nseg[b];
    if (blk >= g_blkoff[b][ns]) return;
    int lo = 0, hi = ns;
    while (hi - lo > 1) { int mid = (lo + hi) >> 1; if (g_blkoff[b][mid] <= blk) lo = mid; else hi = mid; }
    int si = lo;
    int s = g_bnd[b][si], e = g_bnd[b][si + 1], n = e - s;
    int m8 = n >> 3;
    int ncls = (n >> 4) + 1;
    int qtile = blk - g_blkoff[b][si];
    int tid = threadIdx.x;
    int ql = tid >> 4, c = tid & 15;
    int q = qtile * 8 + ql;
    bool act = q < ncls;
    int k0 = act ? ((q == 0) ? m8 : q) : 1;
    const float4* xs = (const float4*)&g_aggf[b][s];   // s multiple of 8 -> 32B aligned
    double dn = (double)n;
    double swd, cwd;
    sincospi(16.0 * (double)k0 / dn, &swd, &cwd);   // omega = 2*pi*8*k0/n
    float2 coeff = ds_from_double(2.0 * cwd);
    float2 s1[8], s2[8];
#pragma unroll
    for (int ph = 0; ph < 8; ++ph) { s1[ph] = make_float2(0, 0); s2[ph] = make_float2(0, 0); }
    int M = n >> 3;
    int Mc = (M + 15) >> 4;
    int t0 = c * Mc, t1 = min(M, t0 + Mc);
    for (int tau = t0; tau < t1; ++tau) {
        float4 va = __ldg(xs + tau * 2);
        float4 vb = __ldg(xs + tau * 2 + 1);
        float v[8] = {va.x, va.y, va.z, va.w, vb.x, vb.y, vb.z, vb.w};
#pragma unroll
        for (int ph = 0; ph < 8; ++ph) {
            float2 tq = s1[ph];
            s1[ph] = ds_add(ds_mul(coeff, tq), ds_fsub(v[ph], s2[ph]));
            s2[ph] = tq;
        }
    }
    // finalize chunk: z = s1 - s2 e^{-iw}; de-rotate by e^{-i w (t1-1)} so each
    // chunk's value equals sum_{tau in chunk} x[8 tau + ph] e^{-i w tau}
    double zr[8], zi[8];
    {
        double rs, rc;
        sincospi(16.0 * (double)k0 * (double)(t1 > 0 ? t1 - 1 : 0) / dn, &rs, &rc);
#pragma unroll
        for (int ph = 0; ph < 8; ++ph) {
            double S1 = ds_to_double(s1[ph]), S2d = ds_to_double(s2[ph]);
            double ar = S1 - cwd * S2d;
            double ai = swd * S2d;
            zr[ph] = rc * ar + rs * ai;     // multiply by e^{-i angle}
            zi[ph] = rc * ai - rs * ar;
        }
    }
    // width-16 tree sum over chunks (deterministic order)
#pragma unroll
    for (int off = 8; off; off >>= 1) {
#pragma unroll
        for (int ph = 0; ph < 8; ++ph) {
            zr[ph] += __shfl_down_sync(0xffffffffu, zr[ph], off, 16);
            zi[ph] += __shfl_down_sync(0xffffffffu, zi[ph], off, 16);
        }
    }
    if (c != 0 || !act) return;

    int half = n >> 1;
    double* pw = &g_pw[b][g_boff[b][si]];
    // q-side bins: k = q + j*m8
#pragma unroll
    for (int j = 0; j <= 4; ++j) {
        int k = q + j * m8;
        if (k < 1 || k > half) continue;
        double c1, s1r;
        sincospi(2.0 * (double)k / dn, &s1r, &c1);
        double cp = 1.0, sp = 0.0, ar = 0.0, ai = 0.0;
#pragma unroll
        for (int ph = 0; ph < 8; ++ph) {
            ar += cp * zr[ph] + sp * zi[ph];
            ai += cp * zi[ph] - sp * zr[ph];
            double ncp = cp * c1 - sp * s1r;
            sp = sp * c1 + cp * s1r;
            cp = ncp;
        }
        pw[k - 1] = ar * ar + ai * ai;
    }
    // mirror-side bins: class q' = m8 - q, k = j*m8 - q  (zi flips sign)
    if (q > 0 && 2 * q != m8) {
#pragma unroll
        for (int j = 1; j <= 4; ++j) {
            int k = j * m8 - q;
            if (k < 1 || k > half) continue;
            double c1, s1r;
            sincospi(2.0 * (double)k / dn, &s1r, &c1);
            double cp = 1.0, sp = 0.0, ar = 0.0, ai = 0.0;
#pragma unroll
            for (int ph = 0; ph < 8; ++ph) {
                double zrm = zr[ph], zim = -zi[ph];
                ar += cp * zrm + sp * zim;
                ai += cp * zim - sp * zrm;
                double ncp = cp * c1 - sp * s1r;
                sp = sp * c1 + cp * s1r;
                cp = ncp;
            }
            pw[k - 1] = ar * ar + ai * ai;
        }
    }
}

// ---------------- 5) per-segment stats + patch length ----------------------------
__global__ __launch_bounds__(256) void k_segstats() {
    int si = blockIdx.x, b = blockIdx.y;
    if (si >= g_nseg[b]) return;
    int s = g_bnd[b][si], e = g_bnd[b][si + 1], n = e - s, m = n >> 1;
    const double* p = &g_pw[b][g_boff[b][si]];
    __shared__ double rs[256], rw[256], rmv[256];
    __shared__ int rmi[256];
    __shared__ double sh_cent, sh_tot;
    int tid = threadIdx.x;
    double tot = 0.0, wf = 0.0, mv = -1.0; int mi = 0x7fffffff;
    for (int kk = tid; kk < m; kk += 256) {
        double pv = p[kk];
        tot += pv; wf += pv * (double)(kk + 1);
        if (pv > mv) { mv = pv; mi = kk; }
    }
    rs[tid] = tot; rw[tid] = wf; rmv[tid] = mv; rmi[tid] = mi;
    __syncthreads();
    for (int off = 128; off; off >>= 1) {
        if (tid < off) {
            rs[tid] += rs[tid + off];
            rw[tid] += rw[tid + off];
            if (rmv[tid + off] > rmv[tid] ||
                (rmv[tid + off] == rmv[tid] && rmi[tid + off] < rmi[tid])) {
                rmv[tid] = rmv[tid + off]; rmi[tid] = rmi[tid + off];
            }
        }
        __syncthreads();
    }
    if (tid == 0) { sh_tot = fmax(rs[0], 1e-8); sh_cent = rw[0] / sh_tot; }
    __syncthreads();
    double cent = sh_cent;
    double vs = 0.0;
    for (int kk = tid; kk < m; kk += 256) {
        double d = (double)(kk + 1) - cent;
        vs += d * d * p[kk];
    }
    __syncthreads();
    rs[tid] = vs;
    __syncthreads();
    for (int off = 128; off; off >>= 1) {
        if (tid < off) rs[tid] += rs[tid + off];
        __syncthreads();
    }
    if (tid == 0) {
        double var = rs[0] / sh_tot;
        double bw = sqrt(fmax(var, 0.0)) / (double)n;
        int dom = rmi[0] + 1;
        double dom_p = (double)n / (double)dom;
        double raw = dom_p / (1.0 + bw);
        int pl = (int)rint(raw * 0.5) * 2;      // round-half-even like numpy
        pl = min(max(pl, 8), 64);
        g_sdom[b][si] = dom_p;
        g_sbw[b][si] = bw;
        g_spl[b][si] = pl;
        g_snp[b][si] = (n + pl - 1) / pl;
    }
}

// ---------------- 6) per-batch token-offset scan + n_tokens out ------------------
__global__ void k_scantok(float* o_ntok) {
    int b = threadIdx.x;
    if (b >= B_) return;
    int ns = g_nseg[b], acc = 0;
    for (int si = 0; si < ns; ++si) { g_toff[b][si] = acc; acc += g_snp[b][si]; }
    g_toff[b][ns] = acc;
    g_ntok[b] = acc;
    o_ntok[b] = (float)acc;
}

// ---------------- 7) token metadata (+ compact token table) -----------------------
__global__ void k_meta(float* o_mask, float* o_start, float* o_end, float* o_center,
                       float* o_span, float* o_regime, int mx) {
    int t = blockIdx.x * blockDim.x + threadIdx.x;
    int b = blockIdx.y;
    if (t >= mx) return;
    int nt = g_ntok[b];
    int ns = g_nseg[b];
    size_t o = (size_t)b * mx + t;
    float mask = 0.f, fs = 0.f, fe = 0.f, fc = 0.f, fp = 0.f, r0 = 0.f, r1 = 0.f, r2 = 0.f;
    if (t < nt && t < MAXTOK_) {
        int lo = 0, hi = ns;
        while (hi - lo > 1) { int mid = (lo + hi) >> 1; if (g_toff[b][mid] <= t) lo = mid; else hi = mid; }
        int si = lo;
        int pi = t - g_toff[b][si];
        int s = g_bnd[b][si], e = g_bnd[b][si + 1];
        int pl = g_spl[b][si];
        int a = s + pi * pl;
        int z = min(e, a + pl);
        g_tok[b][t][0] = a; g_tok[b][t][1] = z;
        mask = 1.f;
        fs = (float)a; fe = (float)z;
        fc = (float)((double)(a + z - 1) * 0.5 / (double)(L_ - 1));
        fp = (float)((double)(z - a) / (double)L_);
        r0 = (float)(g_sdom[b][si] / (double)L_);
        r1 = (float)g_sbw[b][si];
        r2 = (float)((double)(e - s) / (double)L_);
    } else if (t < MAXTOK_) {
        g_tok[b][t][0] = 0; g_tok[b][t][1] = 0;
    }
    o_mask[o] = mask; o_start[o] = fs; o_end[o] = fe;
    o_center[o] = fc; o_span[o] = fp;
    o_regime[o * 3 + 0] = r0; o_regime[o * 3 + 1] = r1; o_regime[o * 3 + 2] = r2;
}

// ---------------- 8) patch gather (resize to 16 anchors) --------------------------
__global__ __launch_bounds__(256) void k_patch(const float* __restrict__ x,
                                               float* __restrict__ o_pat, int mx) {
    int t = blockIdx.x, b = blockIdx.y, tid = threadIdx.x;
    float* outp = o_pat + ((size_t)b * mx + t) * (C_ * 16);
    int nt = min(g_ntok[b], MAXTOK_);
    if (t >= nt) {
        for (int i = tid; i < C_ * 16; i += 256) outp[i] = 0.f;
        return;
    }
    int a = g_tok[b][t][0], z = g_tok[b][t][1];
    int n = z - a;
    double q = (double)n / 16.0;
    const float* xb = x + (size_t)b * C_ * L_;
    for (int i = tid; i < C_ * 16; i += 256) {
        int c = i >> 4, j = i & 15;
        double src = ((double)j + 0.5) * q - 0.5;
        src = fmin(fmax(src, 0.0), (double)(n - 1));
        int i0 = (int)floor(src);
        int i1 = min(i0 + 1, n - 1);
        float w = (float)(src - (double)i0);
        float x0 = xb[(size_t)c * L_ + a + i0];
        float x1 = xb[(size_t)c * L_ + a + i1];
        outp[i] = x0 * (1.0f - w) + x1 * w;
    }
}

// ---------------- host launcher ---------------------------------------------------
extern "C" void kernel_launch(void* const* d_in, const int* in_sizes, int n_in,
                              void* d_out, int out_size) {
    const float* x = (const float*)d_in[0];
    float* out = (float*)d_out;

    // out_size = 32*(1032*mx + 1): patches(32*mx*1024) + 5*(32*mx) + regime(32*mx*3) + 32
    long long mx = ((long long)out_size / 32 - 1) / 1032;
    if (mx < 1) mx = 1;

    float* o_pat    = out;
    float* o_mask   = o_pat + (size_t)B_ * mx * (C_ * 16);
    float* o_start  = o_mask + (size_t)B_ * mx;
    float* o_end    = o_start + (size_t)B_ * mx;
    float* o_center = o_end + (size_t)B_ * mx;
    float* o_span   = o_center + (size_t)B_ * mx;
    float* o_regime = o_span + (size_t)B_ * mx;
    float* o_ntok   = o_regime + (size_t)B_ * mx * 3;

    cudaFuncSetAttribute(k_dp, cudaFuncAttributeMaxDynamicSharedMemorySize, DP_SMEM);

    k_agg<<<dim3(L_ / 256, B_), 256>>>(x);
    k_wfeat<<<dim3((NW_ + 127) / 128, B_), 128>>>();
    k_dp<<<B_, DPT, DP_SMEM>>>();
    k_dft<<<dim3(BCAP_, B_), 128>>>();           // slot 4 -> gets profiled
    k_segstats<<<dim3(MAXSEG_, B_), 256>>>();
    k_scantok<<<1, 32>>>(o_ntok);
    k_meta<<<dim3((unsigned)((mx + 255) / 256), B_), 256>>>(o_mask, o_start, o_end,
                                                            o_center, o_span, o_regime, (int)mx);
    k_patch<<<dim3((unsigned)mx, B_), 256>>>(x, o_pat, (int)mx);
}

// round 13
// speedup vs baseline: 1.1869x; 1.0497x over previous
#include <cuda_runtime.h>
#include <math.h>

#define B_ 32
#define C_ 64
#define L_ 8192
#define W_ 32
#define HOP_ 8
#define NW_ 1021          // (8192-32)/8 + 1 ; last start == L-W so no append
#define NBINS_ 4096       // total spectral bins per batch (sum n_i/2 == L/2)
#define BCAP_ 1088        // dft block capacity per batch
#define MAXSEG_ 1025
#define MAXTOK_ 2048
#define EB 32             // DP end-batch size
#define EG 8              // DP sub-group size (register working set)
#define NG (EB / EG)      // sub-groups per round
#define DPT 512           // DP threads per block
#define NWARP (DPT / 32)

// ================= double-single (df64) arithmetic, fast-math-proof =============
__device__ __forceinline__ float2 ds_from_double(double d) {
    float h = (float)d;
    return make_float2(h, (float)(d - (double)h));
}
__device__ __forceinline__ double ds_to_double(float2 a) {
    return (double)a.x + (double)a.y;
}
__device__ __forceinline__ float2 ds_add(float2 a, float2 b) {
    float s = __fadd_rn(a.x, b.x);
    float v = __fadd_rn(s, -a.x);
    float e = __fadd_rn(__fadd_rn(a.x, -__fadd_rn(s, -v)),
                        __fadd_rn(b.x, -v));
    e = __fadd_rn(e, __fadd_rn(a.y, b.y));
    float hi = __fadd_rn(s, e);
    float lo = __fadd_rn(e, -__fadd_rn(hi, -s));
    return make_float2(hi, lo);
}
__device__ __forceinline__ float2 ds_neg(float2 a) { return make_float2(-a.x, -a.y); }
__device__ __forceinline__ float2 ds_sub(float2 a, float2 b) { return ds_add(a, ds_neg(b)); }
// (a,0) - b  : exact-float minus df64
__device__ __forceinline__ float2 ds_fsub(float a, float2 b) {
    float bx = -b.x;
    float s = __fadd_rn(a, bx);
    float v = __fadd_rn(s, -a);
    float e = __fadd_rn(__fadd_rn(a, -__fadd_rn(s, -v)),
                        __fadd_rn(bx, -v));
    e = __fadd_rn(e, -b.y);
    float hi = __fadd_rn(s, e);
    float lo = __fadd_rn(e, -__fadd_rn(hi, -s));
    return make_float2(hi, lo);
}
__device__ __forceinline__ float2 ds_mul(float2 a, float2 b) {
    float p = __fmul_rn(a.x, b.x);
    float e = __fmaf_rn(a.x, b.x, -p);
    e = __fmaf_rn(a.x, b.y, e);
    e = __fmaf_rn(a.y, b.x, e);
    float hi = __fadd_rn(p, e);
    float lo = __fadd_rn(e, -__fadd_rn(hi, -p));
    return make_float2(hi, lo);
}
__device__ __forceinline__ float2 ds_muf(float a, float2 b) {   // exact-float * df64
    float p = __fmul_rn(a, b.x);
    float e = __fmaf_rn(a, b.x, -p);
    e = __fmaf_rn(a, b.y, e);
    float hi = __fadd_rn(p, e);
    float lo = __fadd_rn(e, -__fadd_rn(hi, -p));
    return make_float2(hi, lo);
}
__device__ __forceinline__ bool ds_lt(float2 a, float2 b) {
    return (a.x < b.x) || (a.x == b.x && a.y < b.y);
}

// ---------------- device scratch (static: no allocation allowed) ----------------
__device__ float  g_aggf[B_][L_];
__device__ double g_feat[B_][NW_][3];
__device__ int    g_bnd[B_][MAXSEG_ + 1];
__device__ int    g_nseg[B_];
__device__ int    g_boff[B_][MAXSEG_ + 1];
__device__ int    g_blkoff[B_][MAXSEG_ + 1];
__device__ double g_pw[B_][NBINS_];
__device__ double g_sdom[B_][MAXSEG_];
__device__ double g_sbw[B_][MAXSEG_];
__device__ int    g_spl[B_][MAXSEG_];
__device__ int    g_snp[B_][MAXSEG_];
__device__ int    g_toff[B_][MAXSEG_ + 1];
__device__ int    g_ntok[B_];
__device__ int    g_tok[B_][MAXTOK_][2];

// ---------------- 1) channel mean (fp32 sequential like numpy; exact in fp32) ----
__global__ void k_agg(const float* __restrict__ x) {
    int t = blockIdx.x * blockDim.x + threadIdx.x;
    int b = blockIdx.y;
    if (t >= L_) return;
    const float* xp = x + (size_t)b * C_ * L_ + t;
    float s = 0.0f;
#pragma unroll 8
    for (int c = 0; c < C_; ++c) s += xp[(size_t)c * L_];
    g_aggf[b][t] = s * (1.0f / 64.0f);
}

// ---------------- 2) per-window spectral features, df64 inner DFT ----------------
__global__ void k_wfeat() {
    __shared__ float2 cs[32], sn[32];
    int tid = threadIdx.x;
    if (tid < 32) {
        cs[tid] = ds_from_double(cospi((double)tid / 16.0));
        sn[tid] = ds_from_double(sinpi((double)tid / 16.0));
    }
    __syncthreads();
    int wi = blockIdx.x * blockDim.x + tid;
    int b = blockIdx.y;
    if (wi >= NW_) return;
    const float4* fr4 = (const float4*)&g_aggf[b][wi * HOP_];
    float fr32[32];
#pragma unroll
    for (int q = 0; q < 8; ++q) {
        float4 v4 = __ldg(fr4 + q);
        fr32[q * 4 + 0] = v4.x; fr32[q * 4 + 1] = v4.y;
        fr32[q * 4 + 2] = v4.z; fr32[q * 4 + 3] = v4.w;
    }
    double p[16];
#pragma unroll
    for (int k = 1; k <= 16; ++k) {
        float2 re = make_float2(0.f, 0.f), im = make_float2(0.f, 0.f);
        int idx = 0;
#pragma unroll
        for (int t = 0; t < 32; ++t) {
            float v = fr32[t];
            re = ds_add(re, ds_muf(v, cs[idx]));
            im = ds_sub(im, ds_muf(v, sn[idx]));
            idx = (idx + k) & 31;
        }
        p[k - 1] = ds_to_double(ds_add(ds_mul(re, re), ds_mul(im, im)));
    }
    double tot = 0.0;
#pragma unroll
    for (int k = 0; k < 16; ++k) tot += p[k];
    double totc = fmax(tot, 1e-8);
    int dom = 1; double mv = p[0];
#pragma unroll
    for (int k = 1; k < 16; ++k) if (p[k] > mv) { mv = p[k]; dom = k + 1; }
    double wf = 0.0;
#pragma unroll
    for (int k = 0; k < 16; ++k) wf += p[k] * (double)(k + 1);
    double cent = wf / totc;
    double vs = 0.0;
#pragma unroll
    for (int k = 0; k < 16; ++k) { double d = (double)(k + 1) - cent; vs += d * d * p[k]; }
    double var = vs / totc;
    double bw = sqrt(fmax(var, 0.0)) / 32.0;
    g_feat[b][wi][0] = (double)dom / 32.0;
    g_feat[b][wi][1] = bw;
    g_feat[b][wi][2] = log1p(tot / 16.0);
}

// ---------------- 3) PELT DP, df64, EB=32 (4 groups), warp wavefront fixup -------
#define DP_SMEM ((7 * (NW_ + 1) + NWARP * EB + EB * EB + EB) * 8 + (NWARP * EB + EB) * 4 + (NW_ + 1) * 2 + 128)

__global__ __launch_bounds__(DPT, 1) void k_dp() {
    extern __shared__ char dsm[];
    float2* s_p0  = (float2*)dsm;
    float2* s_p1  = s_p0 + (NW_ + 1);
    float2* s_p2  = s_p1 + (NW_ + 1);
    float2* s_S2  = s_p2 + (NW_ + 1);
    float2* s_dp  = s_S2 + (NW_ + 1);           // scan scratch only
    float2* s_A   = s_dp + (NW_ + 1);
    float2* s_inv = s_A  + (NW_ + 1);
    float2 (*s_wv)[EB]  = (float2(*)[EB])(s_inv + (NW_ + 1));   // [NWARP][EB]
    float2 (*s_tri)[EB] = (float2(*)[EB])(s_wv + NWARP);        // [EB][EB]
    float2* s_bv = (float2*)(s_tri + EB);                       // [EB]
    int   (*s_wj)[EB] = (int(*)[EB])(s_bv + EB);                // [NWARP][EB]
    int*    s_bj = (int*)(s_wj + NWARP);                        // [EB]
    short*  s_prev = (short*)(s_bj + EB);                       // [NW+1]

    int b = blockIdx.x, tid = threadIdx.x;

    for (int i = tid; i <= NW_; i += DPT)
        s_inv[i] = ds_from_double(i ? 1.0 / (double)i : 0.0);

    // ---- df64 chunked prefix scan of feat / feat^2 (chunk = 8, 128 threads) ----
    float2 (*ch)[6] = (float2(*)[6])(void*)(s_dp + 1);   // scratch aliases s_dp[1..]
    {
        int t = tid;
        if (t < 128) {
            float2 a0 = make_float2(0, 0), a1 = a0, a2 = a0, q0 = a0, q1 = a0, q2 = a0;
            int i0 = t * 8, i1 = min(i0 + 8, NW_);
            for (int i = i0; i < i1; ++i) {
                float2 f0 = ds_from_double(g_feat[b][i][0]);
                float2 f1 = ds_from_double(g_feat[b][i][1]);
                float2 f2 = ds_from_double(g_feat[b][i][2]);
                a0 = ds_add(a0, f0); a1 = ds_add(a1, f1); a2 = ds_add(a2, f2);
                q0 = ds_add(q0, ds_mul(f0, f0));
                q1 = ds_add(q1, ds_mul(f1, f1));
                q2 = ds_add(q2, ds_mul(f2, f2));
            }
            ch[t][0] = a0; ch[t][1] = a1; ch[t][2] = a2;
            ch[t][3] = q0; ch[t][4] = q1; ch[t][5] = q2;
        }
        __syncthreads();
        if (tid == 0) {   // exclusive scan of chunk totals
            float2 r[6];
            for (int d = 0; d < 6; ++d) r[d] = make_float2(0, 0);
            for (int t2 = 0; t2 < 128; ++t2) {
                for (int d = 0; d < 6; ++d) {
                    float2 tmp = ch[t2][d];
                    ch[t2][d] = r[d];
                    r[d] = ds_add(r[d], tmp);
                }
            }
        }
        __syncthreads();
        float2 off[6];
        if (t < 128) { for (int d = 0; d < 6; ++d) off[d] = ch[t][d]; }
        __syncthreads();
        if (t < 128) {
            float2 a0 = off[0], a1 = off[1], a2 = off[2], q0 = off[3], q1 = off[4], q2 = off[5];
            int i0 = t * 8, i1 = min(i0 + 8, NW_);
            for (int i = i0; i < i1; ++i) {
                float2 f0 = ds_from_double(g_feat[b][i][0]);
                float2 f1 = ds_from_double(g_feat[b][i][1]);
                float2 f2 = ds_from_double(g_feat[b][i][2]);
                a0 = ds_add(a0, f0); a1 = ds_add(a1, f1); a2 = ds_add(a2, f2);
                q0 = ds_add(q0, ds_mul(f0, f0));
                q1 = ds_add(q1, ds_mul(f1, f1));
                q2 = ds_add(q2, ds_mul(f2, f2));
                s_p0[i + 1] = a0; s_p1[i + 1] = a1; s_p2[i + 1] = a2;
                s_S2[i + 1] = ds_add(ds_add(q0, q1), q2);
            }
        }
        if (tid == 0) {
            s_p0[0] = make_float2(0, 0); s_p1[0] = make_float2(0, 0);
            s_p2[0] = make_float2(0, 0); s_S2[0] = make_float2(0, 0);
        }
    }
    __syncthreads();
    if (tid == 0) {
        s_A[0] = ds_sub(make_float2(-1.f, 0.f), s_S2[0]);   // A[j] = dp[j] - S2[j]
    }
    __syncthreads();

    const float2 ONE = make_float2(1.f, 0.f);
    const float2 FINF = make_float2(__int_as_float(0x7f800000), 0.f);
    int lane = tid & 31, wrp = tid >> 5;

    for (int e0 = 1; e0 <= NW_; e0 += EB) {
        int kmax = min(EB, NW_ - e0 + 1);

        // ---- phase 1: argmin over j < e0 of cand' = A[j] - ss*inv, NG groups ----
#pragma unroll
        for (int g = 0; g < NG; ++g) {
            int g0 = g * EG;
            int gmax = min(EG, kmax - g0);      // uniform across threads
            if (gmax <= 0) {
                if (lane == 0) {
#pragma unroll
                    for (int k = 0; k < EG; ++k) {
                        s_wv[wrp][g0 + k] = FINF; s_wj[wrp][g0 + k] = -1;
                    }
                }
                continue;
            }
            float2 bv[EG]; int bj[EG];
#pragma unroll
            for (int k = 0; k < EG; ++k) { bv[k] = FINF; bj[k] = -1; }
            for (int j = tid; j < e0; j += DPT) {
                float2 pj0 = s_p0[j], pj1 = s_p1[j], pj2 = s_p2[j];
                float2 Aj = s_A[j];
#pragma unroll
                for (int k = 0; k < EG; ++k) {
                    if (k < gmax) {
                        int end = e0 + g0 + k;
                        float2 d0 = ds_sub(s_p0[end], pj0);
                        float2 d1 = ds_sub(s_p1[end], pj1);
                        float2 d2 = ds_sub(s_p2[end], pj2);
                        float2 ss = ds_add(ds_add(ds_mul(d0, d0), ds_mul(d1, d1)), ds_mul(d2, d2));
                        float2 cand = ds_sub(Aj, ds_mul(ss, s_inv[end - j]));
                        if (ds_lt(cand, bv[k])) { bv[k] = cand; bj[k] = j; } // ascending j: first min
                    }
                }
            }
            // warp-level argmin reduce (smallest j on ties)
#pragma unroll
            for (int k = 0; k < EG; ++k) {
                float2 v = bv[k]; int j = bj[k];
                for (int off = 16; off; off >>= 1) {
                    float2 ov;
                    ov.x = __shfl_down_sync(0xffffffffu, v.x, off);
                    ov.y = __shfl_down_sync(0xffffffffu, v.y, off);
                    int oj = __shfl_down_sync(0xffffffffu, j, off);
                    if (oj >= 0 && (j < 0 || ds_lt(ov, v) || (ov.x == v.x && ov.y == v.y && oj < j))) {
                        v = ov; j = oj;
                    }
                }
                if (lane == 0) { s_wv[wrp][g0 + k] = v; s_wj[wrp][g0 + k] = j; }
            }
        }
        // triangular SSE precompute: all 512 threads, 2 (a,k) pairs each
#pragma unroll
        for (int rep = 0; rep < 2; ++rep) {
            int idx = tid + rep * DPT;
            int a = idx & 31, k = idx >> 5;
            if (a < k && k < kmax) {
                int j = e0 + a, end = e0 + k;
                float2 d0 = ds_sub(s_p0[end], s_p0[j]);
                float2 d1 = ds_sub(s_p1[end], s_p1[j]);
                float2 d2 = ds_sub(s_p2[end], s_p2[j]);
                float2 ss = ds_add(ds_add(ds_mul(d0, d0), ds_mul(d1, d1)), ds_mul(d2, d2));
                s_tri[a][k] = ds_sub(ds_sub(s_S2[end], s_S2[j]),
                                     ds_mul(ss, s_inv[end - j]));
            }
        }
        __syncthreads();
        // cross-warp reduce: 512 threads, EB groups of NWARP(=16)
        {
            int k = tid >> 4, w = tid & 15;
            float2 v = s_wv[w][k]; int j = s_wj[w][k];
            for (int off = 8; off; off >>= 1) {
                float2 ov;
                ov.x = __shfl_down_sync(0xffffffffu, v.x, off, 16);
                ov.y = __shfl_down_sync(0xffffffffu, v.y, off, 16);
                int oj = __shfl_down_sync(0xffffffffu, j, off, 16);
                if (oj >= 0 && (j < 0 || ds_lt(ov, v) || (ov.x == v.x && ov.y == v.y && oj < j))) {
                    v = ov; j = oj;
                }
            }
            if (w == 0) { s_bv[k] = v; s_bj[k] = j; }
        }
        __syncthreads();
        // ---- phase 2: warp-parallel wavefront fixup (lanes 0..kmax-1) ----
        if (tid < 32) {
            bool act = tid < kmax;
            float2 v = FINF; int j = -1;
            if (act) {
                float2 Kk = ds_add(s_S2[e0 + tid], ONE);   // fold back Ke + penalty
                v = ds_add(s_bv[tid], Kk);
                j = s_bj[tid];
            }
#pragma unroll
            for (int a = 0; a < EB - 1; ++a) {
                float2 dpa;
                dpa.x = __shfl_sync(0xffffffffu, v.x, a);
                dpa.y = __shfl_sync(0xffffffffu, v.y, a);
                if (act && tid > a) {
                    float2 cand = ds_add(ds_add(dpa, s_tri[a][tid]), ONE);
                    if (ds_lt(cand, v)) { v = cand; j = e0 + a; }
                }
            }
            if (act) {
                int end = e0 + tid;
                s_prev[end] = (short)j;
                s_A[end] = ds_sub(v, s_S2[end]);
            }
        }
        __syncthreads();
    }

    if (tid == 0) {
        // backtrack (descending), then build ascending boundary list
        int stack[NW_ + 2];
        int cnt = 0, i = NW_;
        while (i > 0) { i = s_prev[i]; stack[cnt++] = i; }
        int nb = 0;
        g_bnd[b][nb++] = 0;
        int last = 0;
        for (int q = cnt - 2; q >= 0; --q) {     // ascending interior changepoints
            int w = stack[q];
            int t = HOP_ * w;
            if (t <= last || t - last < 8 || L_ - t < 8) continue;
            g_bnd[b][nb++] = t;
            last = t;
        }
        g_bnd[b][nb] = L_;
        g_nseg[b] = nb;
        int acc = 0, bacc = 0;
        for (int si = 0; si < nb; ++si) {
            int n = g_bnd[b][si + 1] - g_bnd[b][si];
            g_boff[b][si] = acc;   acc += n >> 1;
            int ncls = (n >> 4) + 1;
            g_blkoff[b][si] = bacc; bacc += (ncls + 15) >> 4;   // 16 classes per block
        }
        g_boff[b][nb] = acc;
        g_blkoff[b][nb] = bacc;
    }
}

// ---------------- 4) segment spectra: D=8 Goertzel, 16 classes x 8 chunks --------
// (R10 geometry, proven fastest; reg-capped to 64 for 8 blocks/SM.)
__global__ __launch_bounds__(128, 8) void k_dft() {
    int blk = blockIdx.x, b = blockIdx.y;
    int ns = g_nseg[b];
    if (blk >= g_blkoff[b][ns]) return;
    int lo = 0, hi = ns;
    while (hi - lo > 1) { int mid = (lo + hi) >> 1; if (g_blkoff[b][mid] <= blk) lo = mid; else hi = mid; }
    int si = lo;
    int s = g_bnd[b][si], e = g_bnd[b][si + 1], n = e - s;
    int m8 = n >> 3;
    int ncls = (n >> 4) + 1;
    int qtile = blk - g_blkoff[b][si];
    int tid = threadIdx.x;
    int ql = tid >> 3, c = tid & 7;
    int q = qtile * 16 + ql;
    bool act = q < ncls;
    int k0 = act ? ((q == 0) ? m8 : q) : 1;
    const float4* xs = (const float4*)&g_aggf[b][s];   // s multiple of 8 -> 32B aligned
    double dn = (double)n;
    double swd, cwd;
    sincospi(16.0 * (double)k0 / dn, &swd, &cwd);   // omega = 2*pi*8*k0/n
    float2 coeff = ds_from_double(2.0 * cwd);
    float2 s1[8], s2[8];
#pragma unroll
    for (int ph = 0; ph < 8; ++ph) { s1[ph] = make_float2(0, 0); s2[ph] = make_float2(0, 0); }
    int M = n >> 3;
    int Mc = (M + 7) >> 3;
    int t0 = c * Mc, t1 = min(M, t0 + Mc);
    for (int tau = t0; tau < t1; ++tau) {
        float4 va = __ldg(xs + tau * 2);
        float4 vb = __ldg(xs + tau * 2 + 1);
        float v[8] = {va.x, va.y, va.z, va.w, vb.x, vb.y, vb.z, vb.w};
#pragma unroll
        for (int ph = 0; ph < 8; ++ph) {
            float2 tq = s1[ph];
            s1[ph] = ds_add(ds_mul(coeff, tq), ds_fsub(v[ph], s2[ph]));
            s2[ph] = tq;
        }
    }
    // finalize chunk: z = s1 - s2 e^{-iw}; de-rotate by e^{-i w (t1-1)} so each
    // chunk's value equals sum_{tau in chunk} x[8 tau + ph] e^{-i w tau}
    double zr[8], zi[8];
    {
        double rs, rc;
        sincospi(16.0 * (double)k0 * (double)(t1 > 0 ? t1 - 1 : 0) / dn, &rs, &rc);
#pragma unroll
        for (int ph = 0; ph < 8; ++ph) {
            double S1 = ds_to_double(s1[ph]), S2d = ds_to_double(s2[ph]);
            double ar = S1 - cwd * S2d;
            double ai = swd * S2d;
            zr[ph] = rc * ar + rs * ai;     // multiply by e^{-i angle}
            zi[ph] = rc * ai - rs * ar;
        }
    }
    // width-8 tree sum over chunks (deterministic order)
#pragma unroll
    for (int off = 4; off; off >>= 1) {
#pragma unroll
        for (int ph = 0; ph < 8; ++ph) {
            zr[ph] += __shfl_down_sync(0xffffffffu, zr[ph], off, 8);
            zi[ph] += __shfl_down_sync(0xffffffffu, zi[ph], off, 8);
        }
    }
    if (c != 0 || !act) return;

    int half = n >> 1;
    double* pw = &g_pw[b][g_boff[b][si]];
    // q-side bins: k = q + j*m8
#pragma unroll
    for (int j = 0; j <= 4; ++j) {
        int k = q + j * m8;
        if (k < 1 || k > half) continue;
        double c1, s1r;
        sincospi(2.0 * (double)k / dn, &s1r, &c1);
        double cp = 1.0, sp = 0.0, ar = 0.0, ai = 0.0;
#pragma unroll
        for (int ph = 0; ph < 8; ++ph) {
            ar += cp * zr[ph] + sp * zi[ph];
            ai += cp * zi[ph] - sp * zr[ph];
            double ncp = cp * c1 - sp * s1r;
            sp = sp * c1 + cp * s1r;
            cp = ncp;
        }
        pw[k - 1] = ar * ar + ai * ai;
    }
    // mirror-side bins: class q' = m8 - q, k = j*m8 - q  (zi flips sign)
    if (q > 0 && 2 * q != m8) {
#pragma unroll
        for (int j = 1; j <= 4; ++j) {
            int k = j * m8 - q;
            if (k < 1 || k > half) continue;
            double c1, s1r;
            sincospi(2.0 * (double)k / dn, &s1r, &c1);
            double cp = 1.0, sp = 0.0, ar = 0.0, ai = 0.0;
#pragma unroll
            for (int ph = 0; ph < 8; ++ph) {
                double zrm = zr[ph], zim = -zi[ph];
                ar += cp * zrm + sp * zim;
                ai += cp * zim - sp * zrm;
                double ncp = cp * c1 - sp * s1r;
                sp = sp * c1 + cp * s1r;
                cp = ncp;
            }
            pw[k - 1] = ar * ar + ai * ai;
        }
    }
}

// ---------------- 5) per-segment stats + patch length ----------------------------
__global__ __launch_bounds__(256) void k_segstats() {
    int si = blockIdx.x, b = blockIdx.y;
    if (si >= g_nseg[b]) return;
    int s = g_bnd[b][si], e = g_bnd[b][si + 1], n = e - s, m = n >> 1;
    const double* p = &g_pw[b][g_boff[b][si]];
    __shared__ double rs[256], rw[256], rmv[256];
    __shared__ int rmi[256];
    __shared__ double sh_cent, sh_tot;
    int tid = threadIdx.x;
    double tot = 0.0, wf = 0.0, mv = -1.0; int mi = 0x7fffffff;
    for (int kk = tid; kk < m; kk += 256) {
        double pv = p[kk];
        tot += pv; wf += pv * (double)(kk + 1);
        if (pv > mv) { mv = pv; mi = kk; }
    }
    rs[tid] = tot; rw[tid] = wf; rmv[tid] = mv; rmi[tid] = mi;
    __syncthreads();
    for (int off = 128; off; off >>= 1) {
        if (tid < off) {
            rs[tid] += rs[tid + off];
            rw[tid] += rw[tid + off];
            if (rmv[tid + off] > rmv[tid] ||
                (rmv[tid + off] == rmv[tid] && rmi[tid + off] < rmi[tid])) {
                rmv[tid] = rmv[tid + off]; rmi[tid] = rmi[tid + off];
            }
        }
        __syncthreads();
    }
    if (tid == 0) { sh_tot = fmax(rs[0], 1e-8); sh_cent = rw[0] / sh_tot; }
    __syncthreads();
    double cent = sh_cent;
    double vs = 0.0;
    for (int kk = tid; kk < m; kk += 256) {
        double d = (double)(kk + 1) - cent;
        vs += d * d * p[kk];
    }
    __syncthreads();
    rs[tid] = vs;
    __syncthreads();
    for (int off = 128; off; off >>= 1) {
        if (tid < off) rs[tid] += rs[tid + off];
        __syncthreads();
    }
    if (tid == 0) {
        double var = rs[0] / sh_tot;
        double bw = sqrt(fmax(var, 0.0)) / (double)n;
        int dom = rmi[0] + 1;
        double dom_p = (double)n / (double)dom;
        double raw = dom_p / (1.0 + bw);
        int pl = (int)rint(raw * 0.5) * 2;      // round-half-even like numpy
        pl = min(max(pl, 8), 64);
        g_sdom[b][si] = dom_p;
        g_sbw[b][si] = bw;
        g_spl[b][si] = pl;
        g_snp[b][si] = (n + pl - 1) / pl;
    }
}

// ---------------- 6) per-batch token-offset scan + n_tokens out ------------------
__global__ void k_scantok(float* o_ntok) {
    int b = threadIdx.x;
    if (b >= B_) return;
    int ns = g_nseg[b], acc = 0;
    for (int si = 0; si < ns; ++si) { g_toff[b][si] = acc; acc += g_snp[b][si]; }
    g_toff[b][ns] = acc;
    g_ntok[b] = acc;
    o_ntok[b] = (float)acc;
}

// ---------------- 7) token metadata (+ compact token table) -----------------------
__global__ void k_meta(float* o_mask, float* o_start, float* o_end, float* o_center,
                       float* o_span, float* o_regime, int mx) {
    int t = blockIdx.x * blockDim.x + threadIdx.x;
    int b = blockIdx.y;
    if (t >= mx) return;
    int nt = g_ntok[b];
    int ns = g_nseg[b];
    size_t o = (size_t)b * mx + t;
    float mask = 0.f, fs = 0.f, fe = 0.f, fc = 0.f, fp = 0.f, r0 = 0.f, r1 = 0.f, r2 = 0.f;
    if (t < nt && t < MAXTOK_) {
        int lo = 0, hi = ns;
        while (hi - lo > 1) { int mid = (lo + hi) >> 1; if (g_toff[b][mid] <= t) lo = mid; else hi = mid; }
        int si = lo;
        int pi = t - g_toff[b][si];
        int s = g_bnd[b][si], e = g_bnd[b][si + 1];
        int pl = g_spl[b][si];
        int a = s + pi * pl;
        int z = min(e, a + pl);
        g_tok[b][t][0] = a; g_tok[b][t][1] = z;
        mask = 1.f;
        fs = (float)a; fe = (float)z;
        fc = (float)((double)(a + z - 1) * 0.5 / (double)(L_ - 1));
        fp = (float)((double)(z - a) / (double)L_);
        r0 = (float)(g_sdom[b][si] / (double)L_);
        r1 = (float)g_sbw[b][si];
        r2 = (float)((double)(e - s) / (double)L_);
    } else if (t < MAXTOK_) {
        g_tok[b][t][0] = 0; g_tok[b][t][1] = 0;
    }
    o_mask[o] = mask; o_start[o] = fs; o_end[o] = fe;
    o_center[o] = fc; o_span[o] = fp;
    o_regime[o * 3 + 0] = r0; o_regime[o * 3 + 1] = r1; o_regime[o * 3 + 2] = r2;
}

// ---------------- 8) patch gather (resize to 16 anchors) --------------------------
__global__ __launch_bounds__(256) void k_patch(const float* __restrict__ x,
                                               float* __restrict__ o_pat, int mx) {
    int t = blockIdx.x, b = blockIdx.y, tid = threadIdx.x;
    float* outp = o_pat + ((size_t)b * mx + t) * (C_ * 16);
    int nt = min(g_ntok[b], MAXTOK_);
    if (t >= nt) {
        for (int i = tid; i < C_ * 16; i += 256) outp[i] = 0.f;
        return;
    }
    int a = g_tok[b][t][0], z = g_tok[b][t][1];
    int n = z - a;
    double q = (double)n / 16.0;
    const float* xb = x + (size_t)b * C_ * L_;
    for (int i = tid; i < C_ * 16; i += 256) {
        int c = i >> 4, j = i & 15;
        double src = ((double)j + 0.5) * q - 0.5;
        src = fmin(fmax(src, 0.0), (double)(n - 1));
        int i0 = (int)floor(src);
        int i1 = min(i0 + 1, n - 1);
        float w = (float)(src - (double)i0);
        float x0 = xb[(size_t)c * L_ + a + i0];
        float x1 = xb[(size_t)c * L_ + a + i1];
        outp[i] = x0 * (1.0f - w) + x1 * w;
    }
}

// ---------------- host launcher ---------------------------------------------------
extern "C" void kernel_launch(void* const* d_in, const int* in_sizes, int n_in,
                              void* d_out, int out_size) {
    const float* x = (const float*)d_in[0];
    float* out = (float*)d_out;

    // out_size = 32*(1032*mx + 1): patches(32*mx*1024) + 5*(32*mx) + regime(32*mx*3) + 32
    long long mx = ((long long)out_size / 32 - 1) / 1032;
    if (mx < 1) mx = 1;

    float* o_pat    = out;
    float* o_mask   = o_pat + (size_t)B_ * mx * (C_ * 16);
    float* o_start  = o_mask + (size_t)B_ * mx;
    float* o_end    = o_start + (size_t)B_ * mx;
    float* o_center = o_end + (size_t)B_ * mx;
    float* o_span   = o_center + (size_t)B_ * mx;
    float* o_regime = o_span + (size_t)B_ * mx;
    float* o_ntok   = o_regime + (size_t)B_ * mx * 3;

    cudaFuncSetAttribute(k_dp, cudaFuncAttributeMaxDynamicSharedMemorySize, DP_SMEM);

    k_agg<<<dim3(L_ / 256, B_), 256>>>(x);
    k_wfeat<<<dim3((NW_ + 127) / 128, B_), 128>>>();
    k_dp<<<B_, DPT, DP_SMEM>>>();
    k_dft<<<dim3(BCAP_, B_), 128>>>();           // slot 4 -> gets profiled
    k_segstats<<<dim3(MAXSEG_, B_), 256>>>();
    k_scantok<<<1, 32>>>(o_ntok);
    k_meta<<<dim3((unsigned)((mx + 255) / 256), B_), 256>>>(o_mask, o_start, o_end,
                                                            o_center, o_span, o_regime, (int)mx);
    k_patch<<<dim3((unsigned)mx, B_), 256>>>(x, o_pat, (int)mx);
}

// round 14
// speedup vs baseline: 1.2651x; 1.0659x over previous
#include <cuda_runtime.h>
#include <math.h>

#define B_ 32
#define C_ 64
#define L_ 8192
#define W_ 32
#define HOP_ 8
#define NW_ 1021          // (8192-32)/8 + 1 ; last start == L-W so no append
#define NBINS_ 4096       // total spectral bins per batch (sum n_i/2 == L/2)
#define BCAP_ 1088        // dft block capacity per batch
#define MAXSEG_ 1025
#define MAXTOK_ 2048
#define EB 32             // DP end-batch size
#define EG 8              // DP sub-group size (register working set)
#define NG (EB / EG)      // sub-groups per round
#define DPT 512           // DP threads per block
#define NWARP (DPT / 32)

// ================= double-single (df64) arithmetic, fast-math-proof =============
__device__ __forceinline__ float2 ds_from_double(double d) {
    float h = (float)d;
    return make_float2(h, (float)(d - (double)h));
}
__device__ __forceinline__ double ds_to_double(float2 a) {
    return (double)a.x + (double)a.y;
}
__device__ __forceinline__ float2 ds_add(float2 a, float2 b) {
    float s = __fadd_rn(a.x, b.x);
    float v = __fadd_rn(s, -a.x);
    float e = __fadd_rn(__fadd_rn(a.x, -__fadd_rn(s, -v)),
                        __fadd_rn(b.x, -v));
    e = __fadd_rn(e, __fadd_rn(a.y, b.y));
    float hi = __fadd_rn(s, e);
    float lo = __fadd_rn(e, -__fadd_rn(hi, -s));
    return make_float2(hi, lo);
}
__device__ __forceinline__ float2 ds_neg(float2 a) { return make_float2(-a.x, -a.y); }
__device__ __forceinline__ float2 ds_sub(float2 a, float2 b) { return ds_add(a, ds_neg(b)); }
// (a,0) - b  : exact-float minus df64
__device__ __forceinline__ float2 ds_fsub(float a, float2 b) {
    float bx = -b.x;
    float s = __fadd_rn(a, bx);
    float v = __fadd_rn(s, -a);
    float e = __fadd_rn(__fadd_rn(a, -__fadd_rn(s, -v)),
                        __fadd_rn(bx, -v));
    e = __fadd_rn(e, -b.y);
    float hi = __fadd_rn(s, e);
    float lo = __fadd_rn(e, -__fadd_rn(hi, -s));
    return make_float2(hi, lo);
}
__device__ __forceinline__ float2 ds_mul(float2 a, float2 b) {
    float p = __fmul_rn(a.x, b.x);
    float e = __fmaf_rn(a.x, b.x, -p);
    e = __fmaf_rn(a.x, b.y, e);
    e = __fmaf_rn(a.y, b.x, e);
    float hi = __fadd_rn(p, e);
    float lo = __fadd_rn(e, -__fadd_rn(hi, -p));
    return make_float2(hi, lo);
}
__device__ __forceinline__ float2 ds_muf(float a, float2 b) {   // exact-float * df64
    float p = __fmul_rn(a, b.x);
    float e = __fmaf_rn(a, b.x, -p);
    e = __fmaf_rn(a, b.y, e);
    float hi = __fadd_rn(p, e);
    float lo = __fadd_rn(e, -__fadd_rn(hi, -p));
    return make_float2(hi, lo);
}
__device__ __forceinline__ bool ds_lt(float2 a, float2 b) {
    return (a.x < b.x) || (a.x == b.x && a.y < b.y);
}

// ---------------- device scratch (static: no allocation allowed) ----------------
__device__ float  g_aggf[B_][L_];
__device__ double g_feat[B_][NW_][3];
__device__ int    g_bnd[B_][MAXSEG_ + 1];
__device__ int    g_nseg[B_];
__device__ int    g_boff[B_][MAXSEG_ + 1];
__device__ int    g_blkoff[B_][MAXSEG_ + 1];
__device__ double g_pw[B_][NBINS_];
__device__ double g_sdom[B_][MAXSEG_];
__device__ double g_sbw[B_][MAXSEG_];
__device__ int    g_spl[B_][MAXSEG_];
__device__ int    g_snp[B_][MAXSEG_];
__device__ int    g_toff[B_][MAXSEG_ + 1];
__device__ int    g_ntok[B_];
__device__ int    g_tok[B_][MAXTOK_][2];

// ---------------- 1) channel mean (fp32 sequential like numpy; exact in fp32) ----
__global__ void k_agg(const float* __restrict__ x) {
    int t = blockIdx.x * blockDim.x + threadIdx.x;
    int b = blockIdx.y;
    if (t >= L_) return;
    const float* xp = x + (size_t)b * C_ * L_ + t;
    float s = 0.0f;
#pragma unroll 8
    for (int c = 0; c < C_; ++c) s += xp[(size_t)c * L_];
    g_aggf[b][t] = s * (1.0f / 64.0f);
}

// ---------------- 2) per-window spectral features, df64 inner DFT ----------------
__global__ void k_wfeat() {
    __shared__ float2 cs[32], sn[32];
    int tid = threadIdx.x;
    if (tid < 32) {
        cs[tid] = ds_from_double(cospi((double)tid / 16.0));
        sn[tid] = ds_from_double(sinpi((double)tid / 16.0));
    }
    __syncthreads();
    int wi = blockIdx.x * blockDim.x + tid;
    int b = blockIdx.y;
    if (wi >= NW_) return;
    const float4* fr4 = (const float4*)&g_aggf[b][wi * HOP_];
    float fr32[32];
#pragma unroll
    for (int q = 0; q < 8; ++q) {
        float4 v4 = __ldg(fr4 + q);
        fr32[q * 4 + 0] = v4.x; fr32[q * 4 + 1] = v4.y;
        fr32[q * 4 + 2] = v4.z; fr32[q * 4 + 3] = v4.w;
    }
    double p[16];
#pragma unroll
    for (int k = 1; k <= 16; ++k) {
        float2 re = make_float2(0.f, 0.f), im = make_float2(0.f, 0.f);
        int idx = 0;
#pragma unroll
        for (int t = 0; t < 32; ++t) {
            float v = fr32[t];
            re = ds_add(re, ds_muf(v, cs[idx]));
            im = ds_sub(im, ds_muf(v, sn[idx]));
            idx = (idx + k) & 31;
        }
        p[k - 1] = ds_to_double(ds_add(ds_mul(re, re), ds_mul(im, im)));
    }
    double tot = 0.0;
#pragma unroll
    for (int k = 0; k < 16; ++k) tot += p[k];
    double totc = fmax(tot, 1e-8);
    int dom = 1; double mv = p[0];
#pragma unroll
    for (int k = 1; k < 16; ++k) if (p[k] > mv) { mv = p[k]; dom = k + 1; }
    double wf = 0.0;
#pragma unroll
    for (int k = 0; k < 16; ++k) wf += p[k] * (double)(k + 1);
    double cent = wf / totc;
    double vs = 0.0;
#pragma unroll
    for (int k = 0; k < 16; ++k) { double d = (double)(k + 1) - cent; vs += d * d * p[k]; }
    double var = vs / totc;
    double bw = sqrt(fmax(var, 0.0)) / 32.0;
    g_feat[b][wi][0] = (double)dom / 32.0;
    g_feat[b][wi][1] = bw;
    g_feat[b][wi][2] = log1p(tot / 16.0);
}

// ---------------- 3) PELT DP, df64, EB=32 (4 groups), warp wavefront fixup -------
#define DP_SMEM ((7 * (NW_ + 1) + NWARP * EB + EB * EB + EB) * 8 + (NWARP * EB + EB) * 4 + (NW_ + 1) * 2 + 128)

__global__ __launch_bounds__(DPT, 1) void k_dp() {
    extern __shared__ char dsm[];
    float2* s_p0  = (float2*)dsm;
    float2* s_p1  = s_p0 + (NW_ + 1);
    float2* s_p2  = s_p1 + (NW_ + 1);
    float2* s_S2  = s_p2 + (NW_ + 1);
    float2* s_dp  = s_S2 + (NW_ + 1);           // scan scratch only
    float2* s_A   = s_dp + (NW_ + 1);
    float2* s_inv = s_A  + (NW_ + 1);
    float2 (*s_wv)[EB]  = (float2(*)[EB])(s_inv + (NW_ + 1));   // [NWARP][EB]
    float2 (*s_tri)[EB] = (float2(*)[EB])(s_wv + NWARP);        // [EB][EB]
    float2* s_bv = (float2*)(s_tri + EB);                       // [EB]
    int   (*s_wj)[EB] = (int(*)[EB])(s_bv + EB);                // [NWARP][EB]
    int*    s_bj = (int*)(s_wj + NWARP);                        // [EB]
    short*  s_prev = (short*)(s_bj + EB);                       // [NW+1]

    int b = blockIdx.x, tid = threadIdx.x;

    for (int i = tid; i <= NW_; i += DPT)
        s_inv[i] = ds_from_double(i ? 1.0 / (double)i : 0.0);

    // ---- df64 chunked prefix scan of feat / feat^2 (chunk = 8, 128 threads) ----
    float2 (*ch)[6] = (float2(*)[6])(void*)(s_dp + 1);   // scratch aliases s_dp[1..]
    {
        int t = tid;
        if (t < 128) {
            float2 a0 = make_float2(0, 0), a1 = a0, a2 = a0, q0 = a0, q1 = a0, q2 = a0;
            int i0 = t * 8, i1 = min(i0 + 8, NW_);
            for (int i = i0; i < i1; ++i) {
                float2 f0 = ds_from_double(g_feat[b][i][0]);
                float2 f1 = ds_from_double(g_feat[b][i][1]);
                float2 f2 = ds_from_double(g_feat[b][i][2]);
                a0 = ds_add(a0, f0); a1 = ds_add(a1, f1); a2 = ds_add(a2, f2);
                q0 = ds_add(q0, ds_mul(f0, f0));
                q1 = ds_add(q1, ds_mul(f1, f1));
                q2 = ds_add(q2, ds_mul(f2, f2));
            }
            ch[t][0] = a0; ch[t][1] = a1; ch[t][2] = a2;
            ch[t][3] = q0; ch[t][4] = q1; ch[t][5] = q2;
        }
        __syncthreads();
        if (tid == 0) {   // exclusive scan of chunk totals
            float2 r[6];
            for (int d = 0; d < 6; ++d) r[d] = make_float2(0, 0);
            for (int t2 = 0; t2 < 128; ++t2) {
                for (int d = 0; d < 6; ++d) {
                    float2 tmp = ch[t2][d];
                    ch[t2][d] = r[d];
                    r[d] = ds_add(r[d], tmp);
                }
            }
        }
        __syncthreads();
        float2 off[6];
        if (t < 128) { for (int d = 0; d < 6; ++d) off[d] = ch[t][d]; }
        __syncthreads();
        if (t < 128) {
            float2 a0 = off[0], a1 = off[1], a2 = off[2], q0 = off[3], q1 = off[4], q2 = off[5];
            int i0 = t * 8, i1 = min(i0 + 8, NW_);
            for (int i = i0; i < i1; ++i) {
                float2 f0 = ds_from_double(g_feat[b][i][0]);
                float2 f1 = ds_from_double(g_feat[b][i][1]);
                float2 f2 = ds_from_double(g_feat[b][i][2]);
                a0 = ds_add(a0, f0); a1 = ds_add(a1, f1); a2 = ds_add(a2, f2);
                q0 = ds_add(q0, ds_mul(f0, f0));
                q1 = ds_add(q1, ds_mul(f1, f1));
                q2 = ds_add(q2, ds_mul(f2, f2));
                s_p0[i + 1] = a0; s_p1[i + 1] = a1; s_p2[i + 1] = a2;
                s_S2[i + 1] = ds_add(ds_add(q0, q1), q2);
            }
        }
        if (tid == 0) {
            s_p0[0] = make_float2(0, 0); s_p1[0] = make_float2(0, 0);
            s_p2[0] = make_float2(0, 0); s_S2[0] = make_float2(0, 0);
        }
    }
    __syncthreads();
    if (tid == 0) {
        s_A[0] = ds_sub(make_float2(-1.f, 0.f), s_S2[0]);   // A[j] = dp[j] - S2[j]
    }
    __syncthreads();

    const float2 ONE = make_float2(1.f, 0.f);
    const float2 FINF = make_float2(__int_as_float(0x7f800000), 0.f);
    int lane = tid & 31, wrp = tid >> 5;

    for (int e0 = 1; e0 <= NW_; e0 += EB) {
        int kmax = min(EB, NW_ - e0 + 1);

        // ---- phase 1: argmin over j < e0 of cand' = A[j] - ss*inv, NG groups ----
#pragma unroll
        for (int g = 0; g < NG; ++g) {
            int g0 = g * EG;
            int gmax = min(EG, kmax - g0);      // uniform across threads
            if (gmax <= 0) {
                if (lane == 0) {
#pragma unroll
                    for (int k = 0; k < EG; ++k) {
                        s_wv[wrp][g0 + k] = FINF; s_wj[wrp][g0 + k] = -1;
                    }
                }
                continue;
            }
            float2 bv[EG]; int bj[EG];
#pragma unroll
            for (int k = 0; k < EG; ++k) { bv[k] = FINF; bj[k] = -1; }
            for (int j = tid; j < e0; j += DPT) {
                float2 pj0 = s_p0[j], pj1 = s_p1[j], pj2 = s_p2[j];
                float2 Aj = s_A[j];
#pragma unroll
                for (int k = 0; k < EG; ++k) {
                    if (k < gmax) {
                        int end = e0 + g0 + k;
                        float2 d0 = ds_sub(s_p0[end], pj0);
                        float2 d1 = ds_sub(s_p1[end], pj1);
                        float2 d2 = ds_sub(s_p2[end], pj2);
                        float2 ss = ds_add(ds_add(ds_mul(d0, d0), ds_mul(d1, d1)), ds_mul(d2, d2));
                        float2 cand = ds_sub(Aj, ds_mul(ss, s_inv[end - j]));
                        if (ds_lt(cand, bv[k])) { bv[k] = cand; bj[k] = j; } // ascending j: first min
                    }
                }
            }
            // warp-level argmin reduce (smallest j on ties)
#pragma unroll
            for (int k = 0; k < EG; ++k) {
                float2 v = bv[k]; int j = bj[k];
                for (int off = 16; off; off >>= 1) {
                    float2 ov;
                    ov.x = __shfl_down_sync(0xffffffffu, v.x, off);
                    ov.y = __shfl_down_sync(0xffffffffu, v.y, off);
                    int oj = __shfl_down_sync(0xffffffffu, j, off);
                    if (oj >= 0 && (j < 0 || ds_lt(ov, v) || (ov.x == v.x && ov.y == v.y && oj < j))) {
                        v = ov; j = oj;
                    }
                }
                if (lane == 0) { s_wv[wrp][g0 + k] = v; s_wj[wrp][g0 + k] = j; }
            }
        }
        // triangular SSE precompute: all 512 threads, 2 (a,k) pairs each
#pragma unroll
        for (int rep = 0; rep < 2; ++rep) {
            int idx = tid + rep * DPT;
            int a = idx & 31, k = idx >> 5;
            if (a < k && k < kmax) {
                int j = e0 + a, end = e0 + k;
                float2 d0 = ds_sub(s_p0[end], s_p0[j]);
                float2 d1 = ds_sub(s_p1[end], s_p1[j]);
                float2 d2 = ds_sub(s_p2[end], s_p2[j]);
                float2 ss = ds_add(ds_add(ds_mul(d0, d0), ds_mul(d1, d1)), ds_mul(d2, d2));
                s_tri[a][k] = ds_sub(ds_sub(s_S2[end], s_S2[j]),
                                     ds_mul(ss, s_inv[end - j]));
            }
        }
        __syncthreads();
        // cross-warp reduce: 512 threads, EB groups of NWARP(=16)
        {
            int k = tid >> 4, w = tid & 15;
            float2 v = s_wv[w][k]; int j = s_wj[w][k];
            for (int off = 8; off; off >>= 1) {
                float2 ov;
                ov.x = __shfl_down_sync(0xffffffffu, v.x, off, 16);
                ov.y = __shfl_down_sync(0xffffffffu, v.y, off, 16);
                int oj = __shfl_down_sync(0xffffffffu, j, off, 16);
                if (oj >= 0 && (j < 0 || ds_lt(ov, v) || (ov.x == v.x && ov.y == v.y && oj < j))) {
                    v = ov; j = oj;
                }
            }
            if (w == 0) { s_bv[k] = v; s_bj[k] = j; }
        }
        __syncthreads();
        // ---- phase 2: warp-parallel wavefront fixup (lanes 0..kmax-1) ----
        if (tid < 32) {
            bool act = tid < kmax;
            float2 v = FINF; int j = -1;
            if (act) {
                float2 Kk = ds_add(s_S2[e0 + tid], ONE);   // fold back Ke + penalty
                v = ds_add(s_bv[tid], Kk);
                j = s_bj[tid];
            }
#pragma unroll
            for (int a = 0; a < EB - 1; ++a) {
                float2 dpa;
                dpa.x = __shfl_sync(0xffffffffu, v.x, a);
                dpa.y = __shfl_sync(0xffffffffu, v.y, a);
                if (act && tid > a) {
                    float2 cand = ds_add(ds_add(dpa, s_tri[a][tid]), ONE);
                    if (ds_lt(cand, v)) { v = cand; j = e0 + a; }
                }
            }
            if (act) {
                int end = e0 + tid;
                s_prev[end] = (short)j;
                s_A[end] = ds_sub(v, s_S2[end]);
            }
        }
        __syncthreads();
    }

    if (tid == 0) {
        // backtrack (descending), then build ascending boundary list
        int stack[NW_ + 2];
        int cnt = 0, i = NW_;
        while (i > 0) { i = s_prev[i]; stack[cnt++] = i; }
        int nb = 0;
        g_bnd[b][nb++] = 0;
        int last = 0;
        for (int q = cnt - 2; q >= 0; --q) {     // ascending interior changepoints
            int w = stack[q];
            int t = HOP_ * w;
            if (t <= last || t - last < 8 || L_ - t < 8) continue;
            g_bnd[b][nb++] = t;
            last = t;
        }
        g_bnd[b][nb] = L_;
        g_nseg[b] = nb;
        int acc = 0, bacc = 0;
        for (int si = 0; si < nb; ++si) {
            int n = g_bnd[b][si + 1] - g_bnd[b][si];
            g_boff[b][si] = acc;   acc += n >> 1;
            int ncls = (n >> 4) + 1;
            g_blkoff[b][si] = bacc; bacc += (ncls + 15) >> 4;   // 16 classes per block
        }
        g_boff[b][nb] = acc;
        g_blkoff[b][nb] = bacc;
    }
}

// ---------------- 4) segment spectra: D=8 Goertzel, 16 classes x 8 chunks --------
// (R10 geometry exactly — measured best: 404 us.)
__global__ __launch_bounds__(128) void k_dft() {
    int blk = blockIdx.x, b = blockIdx.y;
    int ns = g_nseg[b];
    if (blk >= g_blkoff[b][ns]) return;
    int lo = 0, hi = ns;
    while (hi - lo > 1) { int mid = (lo + hi) >> 1; if (g_blkoff[b][mid] <= blk) lo = mid; else hi = mid; }
    int si = lo;
    int s = g_bnd[b][si], e = g_bnd[b][si + 1], n = e - s;
    int m8 = n >> 3;
    int ncls = (n >> 4) + 1;
    int qtile = blk - g_blkoff[b][si];
    int tid = threadIdx.x;
    int ql = tid >> 3, c = tid & 7;
    int q = qtile * 16 + ql;
    bool act = q < ncls;
    int k0 = act ? ((q == 0) ? m8 : q) : 1;
    const float4* xs = (const float4*)&g_aggf[b][s];   // s multiple of 8 -> 32B aligned
    double dn = (double)n;
    double swd, cwd;
    sincospi(16.0 * (double)k0 / dn, &swd, &cwd);   // omega = 2*pi*8*k0/n
    float2 coeff = ds_from_double(2.0 * cwd);
    float2 s1[8], s2[8];
#pragma unroll
    for (int ph = 0; ph < 8; ++ph) { s1[ph] = make_float2(0, 0); s2[ph] = make_float2(0, 0); }
    int M = n >> 3;
    int Mc = (M + 7) >> 3;
    int t0 = c * Mc, t1 = min(M, t0 + Mc);
    for (int tau = t0; tau < t1; ++tau) {
        float4 va = __ldg(xs + tau * 2);
        float4 vb = __ldg(xs + tau * 2 + 1);
        float v[8] = {va.x, va.y, va.z, va.w, vb.x, vb.y, vb.z, vb.w};
#pragma unroll
        for (int ph = 0; ph < 8; ++ph) {
            float2 tq = s1[ph];
            s1[ph] = ds_add(ds_mul(coeff, tq), ds_fsub(v[ph], s2[ph]));
            s2[ph] = tq;
        }
    }
    // finalize chunk: z = s1 - s2 e^{-iw}; de-rotate by e^{-i w (t1-1)} so each
    // chunk's value equals sum_{tau in chunk} x[8 tau + ph] e^{-i w tau}
    double zr[8], zi[8];
    {
        double rs, rc;
        sincospi(16.0 * (double)k0 * (double)(t1 > 0 ? t1 - 1 : 0) / dn, &rs, &rc);
#pragma unroll
        for (int ph = 0; ph < 8; ++ph) {
            double S1 = ds_to_double(s1[ph]), S2d = ds_to_double(s2[ph]);
            double ar = S1 - cwd * S2d;
            double ai = swd * S2d;
            zr[ph] = rc * ar + rs * ai;     // multiply by e^{-i angle}
            zi[ph] = rc * ai - rs * ar;
        }
    }
    // width-8 tree sum over chunks (deterministic order)
#pragma unroll
    for (int off = 4; off; off >>= 1) {
#pragma unroll
        for (int ph = 0; ph < 8; ++ph) {
            zr[ph] += __shfl_down_sync(0xffffffffu, zr[ph], off, 8);
            zi[ph] += __shfl_down_sync(0xffffffffu, zi[ph], off, 8);
        }
    }
    if (c != 0 || !act) return;

    int half = n >> 1;
    double* pw = &g_pw[b][g_boff[b][si]];
    // q-side bins: k = q + j*m8
#pragma unroll
    for (int j = 0; j <= 4; ++j) {
        int k = q + j * m8;
        if (k < 1 || k > half) continue;
        double c1, s1r;
        sincospi(2.0 * (double)k / dn, &s1r, &c1);
        double cp = 1.0, sp = 0.0, ar = 0.0, ai = 0.0;
#pragma unroll
        for (int ph = 0; ph < 8; ++ph) {
            ar += cp * zr[ph] + sp * zi[ph];
            ai += cp * zi[ph] - sp * zr[ph];
            double ncp = cp * c1 - sp * s1r;
            sp = sp * c1 + cp * s1r;
            cp = ncp;
        }
        pw[k - 1] = ar * ar + ai * ai;
    }
    // mirror-side bins: class q' = m8 - q, k = j*m8 - q  (zi flips sign)
    if (q > 0 && 2 * q != m8) {
#pragma unroll
        for (int j = 1; j <= 4; ++j) {
            int k = j * m8 - q;
            if (k < 1 || k > half) continue;
            double c1, s1r;
            sincospi(2.0 * (double)k / dn, &s1r, &c1);
            double cp = 1.0, sp = 0.0, ar = 0.0, ai = 0.0;
#pragma unroll
            for (int ph = 0; ph < 8; ++ph) {
                double zrm = zr[ph], zim = -zi[ph];
                ar += cp * zrm + sp * zim;
                ai += cp * zim - sp * zrm;
                double ncp = cp * c1 - sp * s1r;
                sp = sp * c1 + cp * s1r;
                cp = ncp;
            }
            pw[k - 1] = ar * ar + ai * ai;
        }
    }
}

// ---------------- 5) per-segment stats + patch length ----------------------------
__global__ __launch_bounds__(256) void k_segstats() {
    int si = blockIdx.x, b = blockIdx.y;
    if (si >= g_nseg[b]) return;
    int s = g_bnd[b][si], e = g_bnd[b][si + 1], n = e - s, m = n >> 1;
    const double* p = &g_pw[b][g_boff[b][si]];
    __shared__ double rs[256], rw[256], rmv[256];
    __shared__ int rmi[256];
    __shared__ double sh_cent, sh_tot;
    int tid = threadIdx.x;
    double tot = 0.0, wf = 0.0, mv = -1.0; int mi = 0x7fffffff;
    for (int kk = tid; kk < m; kk += 256) {
        double pv = p[kk];
        tot += pv; wf += pv * (double)(kk + 1);
        if (pv > mv) { mv = pv; mi = kk; }
    }
    rs[tid] = tot; rw[tid] = wf; rmv[tid] = mv; rmi[tid] = mi;
    __syncthreads();
    for (int off = 128; off; off >>= 1) {
        if (tid < off) {
            rs[tid] += rs[tid + off];
            rw[tid] += rw[tid + off];
            if (rmv[tid + off] > rmv[tid] ||
                (rmv[tid + off] == rmv[tid] && rmi[tid + off] < rmi[tid])) {
                rmv[tid] = rmv[tid + off]; rmi[tid] = rmi[tid + off];
            }
        }
        __syncthreads();
    }
    if (tid == 0) { sh_tot = fmax(rs[0], 1e-8); sh_cent = rw[0] / sh_tot; }
    __syncthreads();
    double cent = sh_cent;
    double vs = 0.0;
    for (int kk = tid; kk < m; kk += 256) {
        double d = (double)(kk + 1) - cent;
        vs += d * d * p[kk];
    }
    __syncthreads();
    rs[tid] = vs;
    __syncthreads();
    for (int off = 128; off; off >>= 1) {
        if (tid < off) rs[tid] += rs[tid + off];
        __syncthreads();
    }
    if (tid == 0) {
        double var = rs[0] / sh_tot;
        double bw = sqrt(fmax(var, 0.0)) / (double)n;
        int dom = rmi[0] + 1;
        double dom_p = (double)n / (double)dom;
        double raw = dom_p / (1.0 + bw);
        int pl = (int)rint(raw * 0.5) * 2;      // round-half-even like numpy
        pl = min(max(pl, 8), 64);
        g_sdom[b][si] = dom_p;
        g_sbw[b][si] = bw;
        g_spl[b][si] = pl;
        g_snp[b][si] = (n + pl - 1) / pl;
    }
}

// ---------------- 6) per-batch token-offset scan + n_tokens out ------------------
__global__ void k_scantok(float* o_ntok) {
    int b = threadIdx.x;
    if (b >= B_) return;
    int ns = g_nseg[b], acc = 0;
    for (int si = 0; si < ns; ++si) { g_toff[b][si] = acc; acc += g_snp[b][si]; }
    g_toff[b][ns] = acc;
    g_ntok[b] = acc;
    o_ntok[b] = (float)acc;
}

// ---------------- 7) token metadata (+ compact token table) -----------------------
__global__ void k_meta(float* o_mask, float* o_start, float* o_end, float* o_center,
                       float* o_span, float* o_regime, int mx) {
    int t = blockIdx.x * blockDim.x + threadIdx.x;
    int b = blockIdx.y;
    if (t >= mx) return;
    int nt = g_ntok[b];
    int ns = g_nseg[b];
    size_t o = (size_t)b * mx + t;
    float mask = 0.f, fs = 0.f, fe = 0.f, fc = 0.f, fp = 0.f, r0 = 0.f, r1 = 0.f, r2 = 0.f;
    if (t < nt && t < MAXTOK_) {
        int lo = 0, hi = ns;
        while (hi - lo > 1) { int mid = (lo + hi) >> 1; if (g_toff[b][mid] <= t) lo = mid; else hi = mid; }
        int si = lo;
        int pi = t - g_toff[b][si];
        int s = g_bnd[b][si], e = g_bnd[b][si + 1];
        int pl = g_spl[b][si];
        int a = s + pi * pl;
        int z = min(e, a + pl);
        g_tok[b][t][0] = a; g_tok[b][t][1] = z;
        mask = 1.f;
        fs = (float)a; fe = (float)z;
        fc = (float)((double)(a + z - 1) * 0.5 / (double)(L_ - 1));
        fp = (float)((double)(z - a) / (double)L_);
        r0 = (float)(g_sdom[b][si] / (double)L_);
        r1 = (float)g_sbw[b][si];
        r2 = (float)((double)(e - s) / (double)L_);
    } else if (t < MAXTOK_) {
        g_tok[b][t][0] = 0; g_tok[b][t][1] = 0;
    }
    o_mask[o] = mask; o_start[o] = fs; o_end[o] = fe;
    o_center[o] = fc; o_span[o] = fp;
    o_regime[o * 3 + 0] = r0; o_regime[o * 3 + 1] = r1; o_regime[o * 3 + 2] = r2;
}

// ---------------- 8) patch gather (resize to 16 anchors) --------------------------
__global__ __launch_bounds__(256) void k_patch(const float* __restrict__ x,
                                               float* __restrict__ o_pat, int mx) {
    int t = blockIdx.x, b = blockIdx.y, tid = threadIdx.x;
    float* outp = o_pat + ((size_t)b * mx + t) * (C_ * 16);
    int nt = min(g_ntok[b], MAXTOK_);
    if (t >= nt) {
        for (int i = tid; i < C_ * 16; i += 256) outp[i] = 0.f;
        return;
    }
    int a = g_tok[b][t][0], z = g_tok[b][t][1];
    int n = z - a;
    double q = (double)n / 16.0;
    const float* xb = x + (size_t)b * C_ * L_;
    for (int i = tid; i < C_ * 16; i += 256) {
        int c = i >> 4, j = i & 15;
        double src = ((double)j + 0.5) * q - 0.5;
        src = fmin(fmax(src, 0.0), (double)(n - 1));
        int i0 = (int)floor(src);
        int i1 = min(i0 + 1, n - 1);
        float w = (float)(src - (double)i0);
        float x0 = xb[(size_t)c * L_ + a + i0];
        float x1 = xb[(size_t)c * L_ + a + i1];
        outp[i] = x0 * (1.0f - w) + x1 * w;
    }
}

// ---------------- host launcher ---------------------------------------------------
extern "C" void kernel_launch(void* const* d_in, const int* in_sizes, int n_in,
                              void* d_out, int out_size) {
    const float* x = (const float*)d_in[0];
    float* out = (float*)d_out;

    // out_size = 32*(1032*mx + 1): patches(32*mx*1024) + 5*(32*mx) + regime(32*mx*3) + 32
    long long mx = ((long long)out_size / 32 - 1) / 1032;
    if (mx < 1) mx = 1;

    float* o_pat    = out;
    float* o_mask   = o_pat + (size_t)B_ * mx * (C_ * 16);
    float* o_start  = o_mask + (size_t)B_ * mx;
    float* o_end    = o_start + (size_t)B_ * mx;
    float* o_center = o_end + (size_t)B_ * mx;
    float* o_span   = o_center + (size_t)B_ * mx;
    float* o_regime = o_span + (size_t)B_ * mx;
    float* o_ntok   = o_regime + (size_t)B_ * mx * 3;

    cudaFuncSetAttribute(k_dp, cudaFuncAttributeMaxDynamicSharedMemorySize, DP_SMEM);

    k_agg<<<dim3(L_ / 256, B_), 256>>>(x);
    k_wfeat<<<dim3((NW_ + 127) / 128, B_), 128>>>();
    k_dp<<<B_, DPT, DP_SMEM>>>();
    k_dft<<<dim3(BCAP_, B_), 128>>>();           // slot 4 -> gets profiled
    k_segstats<<<dim3(MAXSEG_, B_), 256>>>();
    k_scantok<<<1, 32>>>(o_ntok);
    k_meta<<<dim3((unsigned)((mx + 255) / 256), B_), 256>>>(o_mask, o_start, o_end,
                                                            o_center, o_span, o_regime, (int)mx);
    k_patch<<<dim3((unsigned)mx, B_), 256>>>(x, o_pat, (int)mx);
}